// round 2
// baseline (speedup 1.0000x reference)
#include <cuda_runtime.h>
#include <cuda_fp16.h>
#include <math.h>
#include <math_constants.h>

// Problem constants
#define NCk 4          // chunks
#define NBk 4          // batch
#define NHk 8          // heads
#define SEQ 4096       // key length
#define TT  4096       // query length
#define CHQ 1024       // queries per chunk
#define ED  64         // head dim
#define MF  128        // nb_features
#define WW  32         // local window
#define NG  128        // NCk*NBk*NHk groups
#define NBLOCK 32      // CHQ/WW query blocks per chunk
#define KVSPLIT 8
#define LOGM 4.852030263919617f

// ---------------- scratch (device globals; no runtime allocation) ----------
__device__ float  g_logk[(size_t)NG * SEQ * MF];         // 256MB
__device__ __half g_phikh[(size_t)NG * SEQ * MF];        // 128MB
__device__ float  g_phiq[(size_t)NG * CHQ * MF];         // 64MB
__device__ float  g_stabk[NG];
__device__ float  g_kv[NG * MF * ED];
__device__ float  g_kvp[(size_t)NG * 2 * KVSPLIT * MF * ED];
__device__ float  g_ksump[NG * KVSPLIT * MF];
__device__ float  g_ksum[NG * MF];
__device__ float  g_pls[NG * CHQ];
__device__ float  g_lr1[NG * CHQ];
__device__ float  g_lrv[(size_t)NG * CHQ * ED];          // 32MB

__device__ __forceinline__ void atomicMaxF(float* addr, float val) {
    int* ai = (int*)addr;
    int old = *ai;
    while (__int_as_float(old) < val) {
        int assumed = old;
        old = atomicCAS(ai, assumed, __float_as_int(val));
        if (old == assumed) break;
    }
}

// ---------------- K0: init ----------------
__global__ void k_init() {
    int t = blockIdx.x * blockDim.x + threadIdx.x;
    if (t < NG) g_stabk[t] = -CUDART_INF_F;
}

// ---------------- K1: logk = k.projT - 0.5||k||^2 ; global max ----------------
struct S1 {
    float skT[ED][129];
    float spT[ED][129];
    float snorm[128];
    float wred[8];
};

__global__ void k_logk(const float* __restrict__ key, const float* __restrict__ proj) {
    extern __shared__ char smem_raw[];
    S1& sm = *reinterpret_cast<S1*>(smem_raw);
    int g = blockIdx.y;
    int c = g >> 5, b = (g >> 3) & 3, h = g & 7;
    int s0 = blockIdx.x * 128;
    int tid = threadIdx.x;

    for (int idx = tid; idx < 128 * ED; idx += 256) {
        int i = idx >> 6, e = idx & 63;
        sm.skT[e][i] = key[(((size_t)b * SEQ + (s0 + i)) * NHk + h) * ED + e];
    }
    for (int idx = tid; idx < MF * ED; idx += 256) {
        int m = idx >> 6, e = idx & 63;
        sm.spT[e][m] = proj[((size_t)c * MF + m) * ED + e];
    }
    __syncthreads();
    if (tid < 128) {
        float s = 0.f;
        #pragma unroll
        for (int e = 0; e < ED; e++) { float v = sm.skT[e][tid]; s += v * v; }
        sm.snorm[tid] = 0.5f * s;
    }
    __syncthreads();

    int tx = tid & 15, ty = tid >> 4;
    float acc[8][8];
    #pragma unroll
    for (int r = 0; r < 8; r++)
        #pragma unroll
        for (int c2 = 0; c2 < 8; c2++) acc[r][c2] = 0.f;

    for (int e = 0; e < ED; e++) {
        float a[8], bb[8];
        #pragma unroll
        for (int r = 0; r < 8; r++) a[r] = sm.skT[e][ty + 16 * r];
        #pragma unroll
        for (int c2 = 0; c2 < 8; c2++) bb[c2] = sm.spT[e][tx + 16 * c2];
        #pragma unroll
        for (int r = 0; r < 8; r++)
            #pragma unroll
            for (int c2 = 0; c2 < 8; c2++) acc[r][c2] = fmaf(a[r], bb[c2], acc[r][c2]);
    }

    float mx = -CUDART_INF_F;
    #pragma unroll
    for (int r = 0; r < 8; r++) {
        int i = ty + 16 * r;
        float nrm = sm.snorm[i];
        size_t rowoff = ((size_t)g * SEQ + (s0 + i)) * MF;
        #pragma unroll
        for (int c2 = 0; c2 < 8; c2++) {
            float v = acc[r][c2] - nrm;
            g_logk[rowoff + tx + 16 * c2] = v;
            mx = fmaxf(mx, v);
        }
    }
    #pragma unroll
    for (int o = 16; o > 0; o >>= 1) mx = fmaxf(mx, __shfl_xor_sync(0xffffffffu, mx, o));
    if ((tid & 31) == 0) sm.wred[tid >> 5] = mx;
    __syncthreads();
    if (tid == 0) {
        float m2 = sm.wred[0];
        #pragma unroll
        for (int w = 1; w < 8; w++) m2 = fmaxf(m2, sm.wred[w]);
        atomicMaxF(&g_stabk[g], m2);
    }
}

// ---------------- K2: fused exp + phi_k(fp16) store + kv partials + ksum ------
__global__ void k_fuse(const float* __restrict__ value) {
    __shared__ float ph[32][MF + 1];
    __shared__ float vv[32][ED + 1];
    __shared__ float ks[256];
    int g = blockIdx.y;
    int split = blockIdx.x;
    int b = (g >> 3) & 3, h = g & 7;
    int s0 = split * (SEQ / KVSPLIT);   // 512 rows per split
    int tid = threadIdx.x;
    int half = tid >> 7;
    int th = tid & 127;
    int tx = th & 7;        // e-group: e = tx + 8*cc
    int ty = th >> 3;       // m-group: m = ty + 16*r
    float stab = g_stabk[g];

    float acc[8][8];
    #pragma unroll
    for (int r = 0; r < 8; r++)
        #pragma unroll
        for (int cc = 0; cc < 8; cc++) acc[r][cc] = 0.f;
    float kpriv = 0.f;

    for (int tile = 0; tile < (SEQ / KVSPLIT) / 32; tile++) {
        int sb = s0 + tile * 32;
        // load logk tile, exp, round to fp16, write out, keep rounded value
        #pragma unroll
        for (int kk = 0; kk < 16; kk++) {
            int idx = tid + kk * 256;
            int s_ = idx >> 7, m = idx & 127;
            size_t gi = ((size_t)g * SEQ + sb + s_) * MF + m;
            float ev = expf(g_logk[gi] - stab);
            __half hh = __float2half_rn(ev);
            g_phikh[gi] = hh;
            float er = __half2float(hh);
            ph[s_][m] = er;
            kpriv += er;
        }
        #pragma unroll
        for (int kk = 0; kk < 8; kk++) {
            int idx = tid + kk * 256;
            int s_ = idx >> 6, e_ = idx & 63;
            vv[s_][e_] = value[(((size_t)b * SEQ + sb + s_) * NHk + h) * ED + e_];
        }
        __syncthreads();
        int rbase = half * 16;
        #pragma unroll 4
        for (int s_ = 0; s_ < 16; s_++) {
            float a[8], bb[8];
            #pragma unroll
            for (int r = 0; r < 8; r++) a[r] = ph[rbase + s_][ty + 16 * r];
            #pragma unroll
            for (int cc = 0; cc < 8; cc++) bb[cc] = vv[rbase + s_][tx + 8 * cc];
            #pragma unroll
            for (int r = 0; r < 8; r++)
                #pragma unroll
                for (int cc = 0; cc < 8; cc++) acc[r][cc] = fmaf(a[r], bb[cc], acc[r][cc]);
        }
        __syncthreads();
    }

    size_t pb = ((size_t)g * 16 + split * 2 + half) * (MF * ED);
    #pragma unroll
    for (int r = 0; r < 8; r++)
        #pragma unroll
        for (int cc = 0; cc < 8; cc++)
            g_kvp[pb + (ty + 16 * r) * ED + (tx + 8 * cc)] = acc[r][cc];

    ks[tid] = kpriv;
    __syncthreads();
    if (tid < 128)
        g_ksump[(g * KVSPLIT + split) * MF + tid] = ks[tid] + ks[tid + 128];
}

// ---------------- K3: reduce kv partials ----------------
__global__ void k_kvred() {
    int i = blockIdx.x * blockDim.x + threadIdx.x;
    if (i < NG * MF * ED) {
        int g = i >> 13;           // MF*ED = 8192
        int me = i & 8191;
        float s = 0.f;
        #pragma unroll
        for (int p = 0; p < 16; p++)
            s += g_kvp[((size_t)g * 16 + p) * (MF * ED) + me];
        g_kv[i] = s;
    }
}

__global__ void k_ksumred() {
    int i = blockIdx.x * blockDim.x + threadIdx.x;
    if (i < NG * MF) {
        int g = i >> 7, m = i & 127;
        float s = 0.f;
        #pragma unroll
        for (int p = 0; p < KVSPLIT; p++)
            s += g_ksump[(g * KVSPLIT + p) * MF + m];
        g_ksum[i] = s;
    }
}

// ---------------- K4: phi_q, stab_q, pls, lr_v, lr_1 ----------------
struct S3 {
    union {
        struct { float sqT[ED][129]; float spT[ED][129]; } in;
        float phiT[MF][132];
    } u;
    float kv[MF][ED + 1];
    float snorm[128];
    float rmax[128][17];
    float stabq[128];
    float ksum[MF];
};

__global__ void k_phiq(const float* __restrict__ query, const float* __restrict__ proj) {
    extern __shared__ char smem_raw[];
    S3& sm = *reinterpret_cast<S3*>(smem_raw);
    int g = blockIdx.y;
    int c = g >> 5, b = (g >> 3) & 3, h = g & 7;
    int q0 = blockIdx.x * 128;
    int tid = threadIdx.x;

    for (int idx = tid; idx < 128 * ED; idx += 256) {
        int i = idx >> 6, e = idx & 63;
        sm.u.in.sqT[e][i] = query[(((size_t)b * TT + (c * CHQ + q0 + i)) * NHk + h) * ED + e];
    }
    for (int idx = tid; idx < MF * ED; idx += 256) {
        int m = idx >> 6, e = idx & 63;
        sm.u.in.spT[e][m] = proj[((size_t)c * MF + m) * ED + e];
    }
    for (int idx = tid; idx < MF * ED; idx += 256)
        sm.kv[idx >> 6][idx & 63] = g_kv[(size_t)g * MF * ED + idx];
    if (tid < MF) sm.ksum[tid] = g_ksum[g * MF + tid];
    __syncthreads();
    if (tid < 128) {
        float s = 0.f;
        #pragma unroll
        for (int e = 0; e < ED; e++) { float v = sm.u.in.sqT[e][tid]; s += v * v; }
        sm.snorm[tid] = 0.5f * s;
    }
    __syncthreads();

    int tx = tid & 15, ty = tid >> 4;
    float acc[8][8];
    #pragma unroll
    for (int r = 0; r < 8; r++)
        #pragma unroll
        for (int c2 = 0; c2 < 8; c2++) acc[r][c2] = 0.f;

    for (int e = 0; e < ED; e++) {
        float a[8], bb[8];
        #pragma unroll
        for (int r = 0; r < 8; r++) a[r] = sm.u.in.sqT[e][ty + 16 * r];
        #pragma unroll
        for (int c2 = 0; c2 < 8; c2++) bb[c2] = sm.u.in.spT[e][tx + 16 * c2];
        #pragma unroll
        for (int r = 0; r < 8; r++)
            #pragma unroll
            for (int c2 = 0; c2 < 8; c2++) acc[r][c2] = fmaf(a[r], bb[c2], acc[r][c2]);
    }

    #pragma unroll
    for (int r = 0; r < 8; r++) {
        int i = ty + 16 * r;
        float nrm = sm.snorm[i];
        float pm = -CUDART_INF_F;
        #pragma unroll
        for (int c2 = 0; c2 < 8; c2++) {
            acc[r][c2] -= nrm;
            pm = fmaxf(pm, acc[r][c2]);
        }
        sm.rmax[i][tx] = pm;
    }
    __syncthreads();   // all GEMM reads of sqT/spT done; union safe after next syncs
    float skv = g_stabk[g];
    if (tid < 128) {
        float m2 = sm.rmax[tid][0];
        #pragma unroll
        for (int j = 1; j < 16; j++) m2 = fmaxf(m2, sm.rmax[tid][j]);
        sm.stabq[tid] = m2;
        g_pls[(size_t)g * CHQ + q0 + tid] = m2 + skv - LOGM;
    }
    __syncthreads();
    // write phi (exp) to transposed smem (overwrites sqT/spT region) + global
    #pragma unroll
    for (int r = 0; r < 8; r++) {
        int i = ty + 16 * r;
        float st = sm.stabq[i];
        size_t rowoff = ((size_t)g * CHQ + q0 + i) * MF;
        #pragma unroll
        for (int c2 = 0; c2 < 8; c2++) {
            float pv = expf(acc[r][c2] - st);
            int m = tx + 16 * c2;
            g_phiq[rowoff + m] = pv;
            sm.u.phiT[m][i] = pv;
        }
    }
    __syncthreads();

    // Phase 2: lr_v = phi(128xMF) . kv(MFxED)
    int tx2 = tid & 15, ty2 = tid >> 4;
    float a2[8][4];
    #pragma unroll
    for (int r = 0; r < 8; r++)
        #pragma unroll
        for (int cc = 0; cc < 4; cc++) a2[r][cc] = 0.f;
    for (int m = 0; m < MF; m++) {
        float av[8], bv[4];
        #pragma unroll
        for (int r = 0; r < 8; r++) av[r] = sm.u.phiT[m][ty2 + 16 * r];
        #pragma unroll
        for (int cc = 0; cc < 4; cc++) bv[cc] = sm.kv[m][tx2 + 16 * cc];
        #pragma unroll
        for (int r = 0; r < 8; r++)
            #pragma unroll
            for (int cc = 0; cc < 4; cc++) a2[r][cc] = fmaf(av[r], bv[cc], a2[r][cc]);
    }
    #pragma unroll
    for (int r = 0; r < 8; r++) {
        int i = ty2 + 16 * r;
        size_t ro = ((size_t)g * CHQ + q0 + i) * ED;
        #pragma unroll
        for (int cc = 0; cc < 4; cc++)
            g_lrv[ro + tx2 + 16 * cc] = a2[r][cc];
    }

    // lr_1 = phi . ksum
    if (tid < 128) {
        float s = 0.f;
        for (int m = 0; m < MF; m++) s = fmaf(sm.u.phiT[m][tid], sm.ksum[m], s);
        g_lr1[(size_t)g * CHQ + q0 + tid] = s;
    }
}

// ---------------- K5: local windows + combination (64-key band) ----------------
struct S5 {
    float qT[ED][WW + 1];       // [64][33]
    float k3T[ED][65];          // 64 keys
    float v3[64][ED + 1];
    float pqT[MF][WW + 1];
    float pk3T[MF][65];
};

__global__ void k_local(const float* __restrict__ query,
                        const float* __restrict__ key,
                        const float* __restrict__ value,
                        float* __restrict__ out) {
    extern __shared__ char smem_raw[];
    S5& sm = *reinterpret_cast<S5*>(smem_raw);
    int g = blockIdx.y;
    int n = blockIdx.x;
    int c = g >> 5, b = (g >> 3) & 3, h = g & 7;
    int tid = threadIdx.x;
    int t0 = n * WW;             // query offset within chunk
    int p0 = t0 - 16;            // key position of j=0  (64-key band)

    for (int idx = tid; idx < WW * ED; idx += 256) {
        int qi = idx >> 6, e = idx & 63;
        sm.qT[e][qi] = query[(((size_t)b * TT + (c * CHQ + t0 + qi)) * NHk + h) * ED + e];
    }
    for (int idx = tid; idx < 64 * ED; idx += 256) {
        int j = idx >> 6, e = idx & 63;
        int pos = p0 + j;
        float kvv = 0.f, vvv = 0.f;
        if (pos >= 0) {
            size_t base = (((size_t)b * SEQ + pos) * NHk + h) * ED + e;
            kvv = key[base];
            vvv = value[base];
        }
        sm.k3T[e][j] = kvv;
        sm.v3[j][e] = vvv;
    }
    for (int idx = tid; idx < WW * MF; idx += 256) {
        int qi = idx >> 7, m = idx & 127;
        sm.pqT[m][qi] = g_phiq[((size_t)g * CHQ + t0 + qi) * MF + m];
    }
    for (int idx = tid; idx < 64 * MF; idx += 256) {
        int j = idx >> 7, m = idx & 127;
        int pos = p0 + j;
        sm.pk3T[m][j] = (pos >= 0) ? __half2float(g_phikh[((size_t)g * SEQ + pos) * MF + m]) : 0.f;
    }
    __syncthreads();

    int lane = tid & 31, wrp = tid >> 5;
    // rows qi = wrp*4 + r, cols j = lane (s0/d0) and lane+32 (s1/d1)

    float s0[4], s1[4], d0[4], d1[4];
    #pragma unroll
    for (int r = 0; r < 4; r++) { s0[r] = 0.f; s1[r] = 0.f; d0[r] = 0.f; d1[r] = 0.f; }

    // scores = q . k3
    for (int e = 0; e < ED; e++) {
        float b0 = sm.k3T[e][lane], b1 = sm.k3T[e][lane + 32];
        #pragma unroll
        for (int r = 0; r < 4; r++) {
            float a = sm.qT[e][wrp * 4 + r];
            s0[r] = fmaf(a, b0, s0[r]);
            s1[r] = fmaf(a, b1, s1[r]);
        }
    }
    // dots = phi_q . phi_k3
    for (int m = 0; m < MF; m++) {
        float b0 = sm.pk3T[m][lane], b1 = sm.pk3T[m][lane + 32];
        #pragma unroll
        for (int r = 0; r < 4; r++) {
            float a = sm.pqT[m][wrp * 4 + r];
            d0[r] = fmaf(a, b0, d0[r]);
            d1[r] = fmaf(a, b1, d1[r]);
        }
    }

    // masks + per-row normalizers
    float scl[4];
    #pragma unroll
    for (int r = 0; r < 4; r++) {
        int qi = wrp * 4 + r;
        // col j valid iff j in [qi, qi+32) and p0 + j >= 0
        int j0 = lane, j1 = lane + 32;
        bool v0 = (j0 >= qi) && (j0 < qi + 32) && (p0 + j0 >= 0);
        bool v1 = (j1 >= qi) && (j1 < qi + 32) && (p0 + j1 >= 0);
        s0[r] = v0 ? s0[r] : -1e24f;
        s1[r] = v1 ? s1[r] : -1e24f;
        d0[r] = v0 ? d0[r] : 0.f;
        d1[r] = v1 ? d1[r] : 0.f;

        float mx = fmaxf(s0[r], s1[r]);
        #pragma unroll
        for (int o = 16; o > 0; o >>= 1) mx = fmaxf(mx, __shfl_xor_sync(0xffffffffu, mx, o));
        float se = expf(s0[r] - mx) + expf(s1[r] - mx);
        #pragma unroll
        for (int o = 16; o > 0; o >>= 1) se += __shfl_xor_sync(0xffffffffu, se, o);
        float lse = mx + logf(se);

        float ds = d0[r] + d1[r];
        #pragma unroll
        for (int o = 16; o > 0; o >>= 1) ds += __shfl_xor_sync(0xffffffffu, ds, o);

        float lr1v = g_lr1[(size_t)g * CHQ + t0 + qi];   // broadcast load
        float plsv = g_pls[(size_t)g * CHQ + t0 + qi];
        float rem = fmaxf(lr1v - ds, 1e-24f);
        float bq = logf(rem) + plsv;
        float hi = fmaxf(lse, bq), lo = fminf(lse, bq);
        float ln = hi + log1pf(expf(lo - hi));
        scl[r] = expf(plsv - ln);
        // p_local in registers
        s0[r] = expf(s0[r] - ln);
        s1[r] = expf(s1[r] - ln);
    }

    // out = p.v3 - dp.v3 (combined later with lrv)
    float op[4][2], wn[4][2];
    #pragma unroll
    for (int r = 0; r < 4; r++)
        #pragma unroll
        for (int ee = 0; ee < 2; ee++) { op[r][ee] = 0.f; wn[r][ee] = 0.f; }

    #pragma unroll 2
    for (int j = 0; j < 64; j++) {
        int src = j & 31;
        bool hiHalf = (j >= 32);
        float bv0 = sm.v3[j][lane];
        float bv1 = sm.v3[j][lane + 32];
        #pragma unroll
        for (int r = 0; r < 4; r++) {
            float pv = __shfl_sync(0xffffffffu, hiHalf ? s1[r] : s0[r], src);
            float dv = __shfl_sync(0xffffffffu, hiHalf ? d1[r] : d0[r], src);
            op[r][0] = fmaf(pv, bv0, op[r][0]);
            op[r][1] = fmaf(pv, bv1, op[r][1]);
            wn[r][0] = fmaf(dv, bv0, wn[r][0]);
            wn[r][1] = fmaf(dv, bv1, wn[r][1]);
        }
    }

    #pragma unroll
    for (int r = 0; r < 4; r++) {
        int qi = wrp * 4 + r;
        size_t lro = ((size_t)g * CHQ + t0 + qi) * ED;
        float lrv0 = g_lrv[lro + lane];
        float lrv1 = g_lrv[lro + lane + 32];
        size_t obase = (((size_t)b * NHk + h) * TT + (c * CHQ + t0 + qi)) * ED;
        out[obase + lane]      = op[r][0] + (lrv0 - wn[r][0]) * scl[r];
        out[obase + lane + 32] = op[r][1] + (lrv1 - wn[r][1]) * scl[r];
    }
}

// ---------------- launch ----------------
extern "C" void kernel_launch(void* const* d_in, const int* in_sizes, int n_in,
                              void* d_out, int out_size) {
    const float* query = (const float*)d_in[0];
    const float* key   = (const float*)d_in[1];
    const float* value = (const float*)d_in[2];
    const float* proj  = (const float*)d_in[3];
    float* out = (float*)d_out;

    cudaFuncSetAttribute(k_logk,  cudaFuncAttributeMaxDynamicSharedMemorySize, (int)sizeof(S1));
    cudaFuncSetAttribute(k_phiq,  cudaFuncAttributeMaxDynamicSharedMemorySize, (int)sizeof(S3));
    cudaFuncSetAttribute(k_local, cudaFuncAttributeMaxDynamicSharedMemorySize, (int)sizeof(S5));

    k_init<<<1, 256>>>();

    dim3 gl(SEQ / 128, NG);
    k_logk<<<gl, 256, sizeof(S1)>>>(key, proj);

    dim3 gf(KVSPLIT, NG);
    k_fuse<<<gf, 256>>>(value);

    k_kvred<<<(NG * MF * ED + 255) / 256, 256>>>();
    k_ksumred<<<(NG * MF + 255) / 256, 256>>>();

    dim3 gq(CHQ / 128, NG);
    k_phiq<<<gq, 256, sizeof(S3)>>>(query, proj);

    dim3 g5(NBLOCK, NG);
    k_local<<<g5, 256, sizeof(S5)>>>(query, key, value, out);
}

// round 3
// speedup vs baseline: 1.0004x; 1.0004x over previous
#include <cuda_runtime.h>
#include <cuda_fp16.h>
#include <math.h>
#include <math_constants.h>

// Problem constants
#define NCk 4          // chunks
#define NBk 4          // batch
#define NHk 8          // heads
#define SEQ 4096       // key length
#define TT  4096       // query length
#define CHQ 1024       // queries per chunk
#define ED  64         // head dim
#define MF  128        // nb_features
#define WW  32         // local window
#define NG  128        // NCk*NBk*NHk groups
#define NBLOCK 32      // CHQ/WW query blocks per chunk
#define KVSPLIT 8
#define LOGM 4.852030263919617f

// ---------------- scratch (device globals; no runtime allocation) ----------
__device__ float  g_logk[(size_t)NG * SEQ * MF];         // 256MB
__device__ __half g_phikh[(size_t)NG * SEQ * MF];        // 128MB
__device__ float  g_phiq[(size_t)NG * CHQ * MF];         // 64MB
__device__ float  g_stabk[NG];
__device__ float  g_kv[NG * MF * ED];
__device__ float  g_kvp[(size_t)NG * 2 * KVSPLIT * MF * ED];
__device__ float  g_ksump[NG * KVSPLIT * MF];
__device__ float  g_ksum[NG * MF];
__device__ float  g_pls[NG * CHQ];
__device__ float  g_lr1[NG * CHQ];
__device__ float  g_lrv[(size_t)NG * CHQ * ED];          // 32MB

__device__ __forceinline__ void atomicMaxF(float* addr, float val) {
    int* ai = (int*)addr;
    int old = *ai;
    while (__int_as_float(old) < val) {
        int assumed = old;
        old = atomicCAS(ai, assumed, __float_as_int(val));
        if (old == assumed) break;
    }
}

// ---------------- K0: init ----------------
__global__ void k_init() {
    int t = blockIdx.x * blockDim.x + threadIdx.x;
    if (t < NG) g_stabk[t] = -CUDART_INF_F;
}

// ---------------- K1: logk = k.projT - 0.5||k||^2 ; global max ----------------
struct S1 {
    float skT[ED][129];
    float spT[ED][129];
    float snorm[128];
    float wred[8];
};

__global__ void k_logk(const float* __restrict__ key, const float* __restrict__ proj) {
    extern __shared__ char smem_raw[];
    S1& sm = *reinterpret_cast<S1*>(smem_raw);
    int g = blockIdx.y;
    int c = g >> 5, b = (g >> 3) & 3, h = g & 7;
    int s0 = blockIdx.x * 128;
    int tid = threadIdx.x;

    for (int idx = tid; idx < 128 * ED; idx += 256) {
        int i = idx >> 6, e = idx & 63;
        sm.skT[e][i] = key[(((size_t)b * SEQ + (s0 + i)) * NHk + h) * ED + e];
    }
    for (int idx = tid; idx < MF * ED; idx += 256) {
        int m = idx >> 6, e = idx & 63;
        sm.spT[e][m] = proj[((size_t)c * MF + m) * ED + e];
    }
    __syncthreads();
    if (tid < 128) {
        float s = 0.f;
        #pragma unroll
        for (int e = 0; e < ED; e++) { float v = sm.skT[e][tid]; s += v * v; }
        sm.snorm[tid] = 0.5f * s;
    }
    __syncthreads();

    int tx = tid & 15, ty = tid >> 4;
    float acc[8][8];
    #pragma unroll
    for (int r = 0; r < 8; r++)
        #pragma unroll
        for (int c2 = 0; c2 < 8; c2++) acc[r][c2] = 0.f;

    for (int e = 0; e < ED; e++) {
        float a[8], bb[8];
        #pragma unroll
        for (int r = 0; r < 8; r++) a[r] = sm.skT[e][ty + 16 * r];
        #pragma unroll
        for (int c2 = 0; c2 < 8; c2++) bb[c2] = sm.spT[e][tx + 16 * c2];
        #pragma unroll
        for (int r = 0; r < 8; r++)
            #pragma unroll
            for (int c2 = 0; c2 < 8; c2++) acc[r][c2] = fmaf(a[r], bb[c2], acc[r][c2]);
    }

    float mx = -CUDART_INF_F;
    #pragma unroll
    for (int r = 0; r < 8; r++) {
        int i = ty + 16 * r;
        float nrm = sm.snorm[i];
        size_t rowoff = ((size_t)g * SEQ + (s0 + i)) * MF;
        #pragma unroll
        for (int c2 = 0; c2 < 8; c2++) {
            float v = acc[r][c2] - nrm;
            g_logk[rowoff + tx + 16 * c2] = v;
            mx = fmaxf(mx, v);
        }
    }
    #pragma unroll
    for (int o = 16; o > 0; o >>= 1) mx = fmaxf(mx, __shfl_xor_sync(0xffffffffu, mx, o));
    if ((tid & 31) == 0) sm.wred[tid >> 5] = mx;
    __syncthreads();
    if (tid == 0) {
        float m2 = sm.wred[0];
        #pragma unroll
        for (int w = 1; w < 8; w++) m2 = fmaxf(m2, sm.wred[w]);
        atomicMaxF(&g_stabk[g], m2);
    }
}

// ---------------- K2: fused exp + phi_k(fp16) store + kv partials + ksum ------
__global__ void k_fuse(const float* __restrict__ value) {
    __shared__ float ph[32][MF + 1];
    __shared__ float vv[32][ED + 1];
    __shared__ float ks[256];
    int g = blockIdx.y;
    int split = blockIdx.x;
    int b = (g >> 3) & 3, h = g & 7;
    int s0 = split * (SEQ / KVSPLIT);   // 512 rows per split
    int tid = threadIdx.x;
    int half = tid >> 7;
    int th = tid & 127;
    int tx = th & 7;        // e-group: e = tx + 8*cc
    int ty = th >> 3;       // m-group: m = ty + 16*r
    float stab = g_stabk[g];

    float acc[8][8];
    #pragma unroll
    for (int r = 0; r < 8; r++)
        #pragma unroll
        for (int cc = 0; cc < 8; cc++) acc[r][cc] = 0.f;
    float kpriv = 0.f;

    for (int tile = 0; tile < (SEQ / KVSPLIT) / 32; tile++) {
        int sb = s0 + tile * 32;
        // load logk tile, exp, round to fp16, write out, keep rounded value
        #pragma unroll
        for (int kk = 0; kk < 16; kk++) {
            int idx = tid + kk * 256;
            int s_ = idx >> 7, m = idx & 127;
            size_t gi = ((size_t)g * SEQ + sb + s_) * MF + m;
            float ev = expf(g_logk[gi] - stab);
            __half hh = __float2half_rn(ev);
            g_phikh[gi] = hh;
            float er = __half2float(hh);
            ph[s_][m] = er;
            kpriv += er;
        }
        #pragma unroll
        for (int kk = 0; kk < 8; kk++) {
            int idx = tid + kk * 256;
            int s_ = idx >> 6, e_ = idx & 63;
            vv[s_][e_] = value[(((size_t)b * SEQ + sb + s_) * NHk + h) * ED + e_];
        }
        __syncthreads();
        int rbase = half * 16;
        #pragma unroll 4
        for (int s_ = 0; s_ < 16; s_++) {
            float a[8], bb[8];
            #pragma unroll
            for (int r = 0; r < 8; r++) a[r] = ph[rbase + s_][ty + 16 * r];
            #pragma unroll
            for (int cc = 0; cc < 8; cc++) bb[cc] = vv[rbase + s_][tx + 8 * cc];
            #pragma unroll
            for (int r = 0; r < 8; r++)
                #pragma unroll
                for (int cc = 0; cc < 8; cc++) acc[r][cc] = fmaf(a[r], bb[cc], acc[r][cc]);
        }
        __syncthreads();
    }

    size_t pb = ((size_t)g * 16 + split * 2 + half) * (MF * ED);
    #pragma unroll
    for (int r = 0; r < 8; r++)
        #pragma unroll
        for (int cc = 0; cc < 8; cc++)
            g_kvp[pb + (ty + 16 * r) * ED + (tx + 8 * cc)] = acc[r][cc];

    ks[tid] = kpriv;
    __syncthreads();
    if (tid < 128)
        g_ksump[(g * KVSPLIT + split) * MF + tid] = ks[tid] + ks[tid + 128];
}

// ---------------- K3: reduce kv partials ----------------
__global__ void k_kvred() {
    int i = blockIdx.x * blockDim.x + threadIdx.x;
    if (i < NG * MF * ED) {
        int g = i >> 13;           // MF*ED = 8192
        int me = i & 8191;
        float s = 0.f;
        #pragma unroll
        for (int p = 0; p < 16; p++)
            s += g_kvp[((size_t)g * 16 + p) * (MF * ED) + me];
        g_kv[i] = s;
    }
}

__global__ void k_ksumred() {
    int i = blockIdx.x * blockDim.x + threadIdx.x;
    if (i < NG * MF) {
        int g = i >> 7, m = i & 127;
        float s = 0.f;
        #pragma unroll
        for (int p = 0; p < KVSPLIT; p++)
            s += g_ksump[(g * KVSPLIT + p) * MF + m];
        g_ksum[i] = s;
    }
}

// ---------------- K4: phi_q, stab_q, pls, lr_v, lr_1 ----------------
struct S3 {
    union {
        struct { float sqT[ED][129]; float spT[ED][129]; } in;
        float phiT[MF][132];
    } u;
    float kv[MF][ED + 1];
    float snorm[128];
    float rmax[128][17];
    float stabq[128];
    float ksum[MF];
};

__global__ void k_phiq(const float* __restrict__ query, const float* __restrict__ proj) {
    extern __shared__ char smem_raw[];
    S3& sm = *reinterpret_cast<S3*>(smem_raw);
    int g = blockIdx.y;
    int c = g >> 5, b = (g >> 3) & 3, h = g & 7;
    int q0 = blockIdx.x * 128;
    int tid = threadIdx.x;

    for (int idx = tid; idx < 128 * ED; idx += 256) {
        int i = idx >> 6, e = idx & 63;
        sm.u.in.sqT[e][i] = query[(((size_t)b * TT + (c * CHQ + q0 + i)) * NHk + h) * ED + e];
    }
    for (int idx = tid; idx < MF * ED; idx += 256) {
        int m = idx >> 6, e = idx & 63;
        sm.u.in.spT[e][m] = proj[((size_t)c * MF + m) * ED + e];
    }
    for (int idx = tid; idx < MF * ED; idx += 256)
        sm.kv[idx >> 6][idx & 63] = g_kv[(size_t)g * MF * ED + idx];
    if (tid < MF) sm.ksum[tid] = g_ksum[g * MF + tid];
    __syncthreads();
    if (tid < 128) {
        float s = 0.f;
        #pragma unroll
        for (int e = 0; e < ED; e++) { float v = sm.u.in.sqT[e][tid]; s += v * v; }
        sm.snorm[tid] = 0.5f * s;
    }
    __syncthreads();

    int tx = tid & 15, ty = tid >> 4;
    float acc[8][8];
    #pragma unroll
    for (int r = 0; r < 8; r++)
        #pragma unroll
        for (int c2 = 0; c2 < 8; c2++) acc[r][c2] = 0.f;

    for (int e = 0; e < ED; e++) {
        float a[8], bb[8];
        #pragma unroll
        for (int r = 0; r < 8; r++) a[r] = sm.u.in.sqT[e][ty + 16 * r];
        #pragma unroll
        for (int c2 = 0; c2 < 8; c2++) bb[c2] = sm.u.in.spT[e][tx + 16 * c2];
        #pragma unroll
        for (int r = 0; r < 8; r++)
            #pragma unroll
            for (int c2 = 0; c2 < 8; c2++) acc[r][c2] = fmaf(a[r], bb[c2], acc[r][c2]);
    }

    #pragma unroll
    for (int r = 0; r < 8; r++) {
        int i = ty + 16 * r;
        float nrm = sm.snorm[i];
        float pm = -CUDART_INF_F;
        #pragma unroll
        for (int c2 = 0; c2 < 8; c2++) {
            acc[r][c2] -= nrm;
            pm = fmaxf(pm, acc[r][c2]);
        }
        sm.rmax[i][tx] = pm;
    }
    __syncthreads();   // all GEMM reads of sqT/spT done; union safe after next syncs
    float skv = g_stabk[g];
    if (tid < 128) {
        float m2 = sm.rmax[tid][0];
        #pragma unroll
        for (int j = 1; j < 16; j++) m2 = fmaxf(m2, sm.rmax[tid][j]);
        sm.stabq[tid] = m2;
        g_pls[(size_t)g * CHQ + q0 + tid] = m2 + skv - LOGM;
    }
    __syncthreads();
    // write phi (exp) to transposed smem (overwrites sqT/spT region) + global
    #pragma unroll
    for (int r = 0; r < 8; r++) {
        int i = ty + 16 * r;
        float st = sm.stabq[i];
        size_t rowoff = ((size_t)g * CHQ + q0 + i) * MF;
        #pragma unroll
        for (int c2 = 0; c2 < 8; c2++) {
            float pv = expf(acc[r][c2] - st);
            int m = tx + 16 * c2;
            g_phiq[rowoff + m] = pv;
            sm.u.phiT[m][i] = pv;
        }
    }
    __syncthreads();

    // Phase 2: lr_v = phi(128xMF) . kv(MFxED)
    int tx2 = tid & 15, ty2 = tid >> 4;
    float a2[8][4];
    #pragma unroll
    for (int r = 0; r < 8; r++)
        #pragma unroll
        for (int cc = 0; cc < 4; cc++) a2[r][cc] = 0.f;
    for (int m = 0; m < MF; m++) {
        float av[8], bv[4];
        #pragma unroll
        for (int r = 0; r < 8; r++) av[r] = sm.u.phiT[m][ty2 + 16 * r];
        #pragma unroll
        for (int cc = 0; cc < 4; cc++) bv[cc] = sm.kv[m][tx2 + 16 * cc];
        #pragma unroll
        for (int r = 0; r < 8; r++)
            #pragma unroll
            for (int cc = 0; cc < 4; cc++) a2[r][cc] = fmaf(av[r], bv[cc], a2[r][cc]);
    }
    #pragma unroll
    for (int r = 0; r < 8; r++) {
        int i = ty2 + 16 * r;
        size_t ro = ((size_t)g * CHQ + q0 + i) * ED;
        #pragma unroll
        for (int cc = 0; cc < 4; cc++)
            g_lrv[ro + tx2 + 16 * cc] = a2[r][cc];
    }

    // lr_1 = phi . ksum
    if (tid < 128) {
        float s = 0.f;
        for (int m = 0; m < MF; m++) s = fmaf(sm.u.phiT[m][tid], sm.ksum[m], s);
        g_lr1[(size_t)g * CHQ + q0 + tid] = s;
    }
}

// ---------------- K5: local windows + combination (64-key band) ----------------
struct S5 {
    float qT[ED][WW + 1];       // [64][33]
    float k3T[ED][65];          // 64 keys
    float v3[64][ED + 1];
    float pqT[MF][WW + 1];
    float pk3T[MF][65];
};

__global__ void k_local(const float* __restrict__ query,
                        const float* __restrict__ key,
                        const float* __restrict__ value,
                        float* __restrict__ out) {
    extern __shared__ char smem_raw[];
    S5& sm = *reinterpret_cast<S5*>(smem_raw);
    int g = blockIdx.y;
    int n = blockIdx.x;
    int c = g >> 5, b = (g >> 3) & 3, h = g & 7;
    int tid = threadIdx.x;
    int t0 = n * WW;             // query offset within chunk
    int p0 = t0 - 16;            // key position of j=0  (64-key band)

    for (int idx = tid; idx < WW * ED; idx += 256) {
        int qi = idx >> 6, e = idx & 63;
        sm.qT[e][qi] = query[(((size_t)b * TT + (c * CHQ + t0 + qi)) * NHk + h) * ED + e];
    }
    for (int idx = tid; idx < 64 * ED; idx += 256) {
        int j = idx >> 6, e = idx & 63;
        int pos = p0 + j;
        float kvv = 0.f, vvv = 0.f;
        if (pos >= 0) {
            size_t base = (((size_t)b * SEQ + pos) * NHk + h) * ED + e;
            kvv = key[base];
            vvv = value[base];
        }
        sm.k3T[e][j] = kvv;
        sm.v3[j][e] = vvv;
    }
    for (int idx = tid; idx < WW * MF; idx += 256) {
        int qi = idx >> 7, m = idx & 127;
        sm.pqT[m][qi] = g_phiq[((size_t)g * CHQ + t0 + qi) * MF + m];
    }
    for (int idx = tid; idx < 64 * MF; idx += 256) {
        int j = idx >> 7, m = idx & 127;
        int pos = p0 + j;
        sm.pk3T[m][j] = (pos >= 0) ? __half2float(g_phikh[((size_t)g * SEQ + pos) * MF + m]) : 0.f;
    }
    __syncthreads();

    int lane = tid & 31, wrp = tid >> 5;
    // rows qi = wrp*4 + r, cols j = lane (s0/d0) and lane+32 (s1/d1)

    float s0[4], s1[4], d0[4], d1[4];
    #pragma unroll
    for (int r = 0; r < 4; r++) { s0[r] = 0.f; s1[r] = 0.f; d0[r] = 0.f; d1[r] = 0.f; }

    // scores = q . k3
    for (int e = 0; e < ED; e++) {
        float b0 = sm.k3T[e][lane], b1 = sm.k3T[e][lane + 32];
        #pragma unroll
        for (int r = 0; r < 4; r++) {
            float a = sm.qT[e][wrp * 4 + r];
            s0[r] = fmaf(a, b0, s0[r]);
            s1[r] = fmaf(a, b1, s1[r]);
        }
    }
    // dots = phi_q . phi_k3
    for (int m = 0; m < MF; m++) {
        float b0 = sm.pk3T[m][lane], b1 = sm.pk3T[m][lane + 32];
        #pragma unroll
        for (int r = 0; r < 4; r++) {
            float a = sm.pqT[m][wrp * 4 + r];
            d0[r] = fmaf(a, b0, d0[r]);
            d1[r] = fmaf(a, b1, d1[r]);
        }
    }

    // masks + per-row normalizers
    float scl[4];
    #pragma unroll
    for (int r = 0; r < 4; r++) {
        int qi = wrp * 4 + r;
        // col j valid iff j in [qi, qi+32) and p0 + j >= 0
        int j0 = lane, j1 = lane + 32;
        bool v0 = (j0 >= qi) && (j0 < qi + 32) && (p0 + j0 >= 0);
        bool v1 = (j1 >= qi) && (j1 < qi + 32) && (p0 + j1 >= 0);
        s0[r] = v0 ? s0[r] : -1e24f;
        s1[r] = v1 ? s1[r] : -1e24f;
        d0[r] = v0 ? d0[r] : 0.f;
        d1[r] = v1 ? d1[r] : 0.f;

        float mx = fmaxf(s0[r], s1[r]);
        #pragma unroll
        for (int o = 16; o > 0; o >>= 1) mx = fmaxf(mx, __shfl_xor_sync(0xffffffffu, mx, o));
        float se = expf(s0[r] - mx) + expf(s1[r] - mx);
        #pragma unroll
        for (int o = 16; o > 0; o >>= 1) se += __shfl_xor_sync(0xffffffffu, se, o);
        float lse = mx + logf(se);

        float ds = d0[r] + d1[r];
        #pragma unroll
        for (int o = 16; o > 0; o >>= 1) ds += __shfl_xor_sync(0xffffffffu, ds, o);

        float lr1v = g_lr1[(size_t)g * CHQ + t0 + qi];   // broadcast load
        float plsv = g_pls[(size_t)g * CHQ + t0 + qi];
        float rem = fmaxf(lr1v - ds, 1e-24f);
        float bq = logf(rem) + plsv;
        float hi = fmaxf(lse, bq), lo = fminf(lse, bq);
        float ln = hi + log1pf(expf(lo - hi));
        scl[r] = expf(plsv - ln);
        // p_local in registers
        s0[r] = expf(s0[r] - ln);
        s1[r] = expf(s1[r] - ln);
    }

    // out = p.v3 - dp.v3 (combined later with lrv)
    float op[4][2], wn[4][2];
    #pragma unroll
    for (int r = 0; r < 4; r++)
        #pragma unroll
        for (int ee = 0; ee < 2; ee++) { op[r][ee] = 0.f; wn[r][ee] = 0.f; }

    #pragma unroll 2
    for (int j = 0; j < 64; j++) {
        int src = j & 31;
        bool hiHalf = (j >= 32);
        float bv0 = sm.v3[j][lane];
        float bv1 = sm.v3[j][lane + 32];
        #pragma unroll
        for (int r = 0; r < 4; r++) {
            float pv = __shfl_sync(0xffffffffu, hiHalf ? s1[r] : s0[r], src);
            float dv = __shfl_sync(0xffffffffu, hiHalf ? d1[r] : d0[r], src);
            op[r][0] = fmaf(pv, bv0, op[r][0]);
            op[r][1] = fmaf(pv, bv1, op[r][1]);
            wn[r][0] = fmaf(dv, bv0, wn[r][0]);
            wn[r][1] = fmaf(dv, bv1, wn[r][1]);
        }
    }

    #pragma unroll
    for (int r = 0; r < 4; r++) {
        int qi = wrp * 4 + r;
        size_t lro = ((size_t)g * CHQ + t0 + qi) * ED;
        float lrv0 = g_lrv[lro + lane];
        float lrv1 = g_lrv[lro + lane + 32];
        size_t obase = (((size_t)b * NHk + h) * TT + (c * CHQ + t0 + qi)) * ED;
        out[obase + lane]      = op[r][0] + (lrv0 - wn[r][0]) * scl[r];
        out[obase + lane + 32] = op[r][1] + (lrv1 - wn[r][1]) * scl[r];
    }
}

// ---------------- launch ----------------
extern "C" void kernel_launch(void* const* d_in, const int* in_sizes, int n_in,
                              void* d_out, int out_size) {
    const float* query = (const float*)d_in[0];
    const float* key   = (const float*)d_in[1];
    const float* value = (const float*)d_in[2];
    const float* proj  = (const float*)d_in[3];
    float* out = (float*)d_out;

    cudaFuncSetAttribute(k_logk,  cudaFuncAttributeMaxDynamicSharedMemorySize, (int)sizeof(S1));
    cudaFuncSetAttribute(k_phiq,  cudaFuncAttributeMaxDynamicSharedMemorySize, (int)sizeof(S3));
    cudaFuncSetAttribute(k_local, cudaFuncAttributeMaxDynamicSharedMemorySize, (int)sizeof(S5));

    k_init<<<1, 256>>>();

    dim3 gl(SEQ / 128, NG);
    k_logk<<<gl, 256, sizeof(S1)>>>(key, proj);

    dim3 gf(KVSPLIT, NG);
    k_fuse<<<gf, 256>>>(value);

    k_kvred<<<(NG * MF * ED + 255) / 256, 256>>>();
    k_ksumred<<<(NG * MF + 255) / 256, 256>>>();

    dim3 gq(CHQ / 128, NG);
    k_phiq<<<gq, 256, sizeof(S3)>>>(query, proj);

    dim3 g5(NBLOCK, NG);
    k_local<<<g5, 256, sizeof(S5)>>>(query, key, value, out);
}

// round 4
// speedup vs baseline: 1.8333x; 1.8325x over previous
#include <cuda_runtime.h>
#include <cuda_fp16.h>
#include <math.h>
#include <math_constants.h>

#define SEQ 4096
#define TT  4096
#define CHQ 1024
#define ED  64
#define MF  128
#define NHk 8
#define NG  128
#define LOGM 4.852030263919617f

__device__ __half g_phikh[(size_t)NG*SEQ*MF];
__device__ float  g_phiq[(size_t)NG*CHQ*MF];
__device__ float  g_tstab[NG*32];
__device__ float  g_pstab[NG*8];
__device__ float  g_stabk[NG];
__device__ float  g_kvp[(size_t)NG*8*MF*ED];
__device__ float  g_kv[NG*MF*ED];
__device__ float  g_ksump[NG*8*MF];
__device__ float  g_ksum[NG*MF];
__device__ float  g_pls[NG*CHQ];
__device__ float  g_lr1[NG*CHQ];
__device__ float  g_lrv[(size_t)NG*CHQ*ED];

__device__ __forceinline__ void mma16816(float* c, unsigned a0,unsigned a1,unsigned a2,unsigned a3,
                                         unsigned b0,unsigned b1){
  asm volatile("mma.sync.aligned.m16n8k16.row.col.f32.f16.f16.f32 "
    "{%0,%1,%2,%3},{%4,%5,%6,%7},{%8,%9},{%0,%1,%2,%3};"
    : "+f"(c[0]),"+f"(c[1]),"+f"(c[2]),"+f"(c[3])
    : "r"(a0),"r"(a1),"r"(a2),"r"(a3),"r"(b0),"r"(b1));
}
__device__ __forceinline__ unsigned ldu(const __half* p){ return *(const unsigned*)p; }
__device__ __forceinline__ void split16(float x, __half& h, __half& l){
  h = __float2half_rn(x); l = __float2half_rn(x - __half2float(h));
}

// ======== K1: fused logk mma + phi_k(fp16) + kv mma + ksum (per-tile stabs) ====
struct SP {
  __half Bp[128][200];                      // proj split [ph|ph|pl]
  union { __half Ak[128][200]; __half phiA[128][136]; } u;  // key split [kh|kl|kh] / phi[m][s]
  float logkS[128][132];
  __half vT[64][136];
  float snorm[128];
  float wred[8];
  float ks2[256];
};

__global__ void __launch_bounds__(256,1)
k_phik(const float* __restrict__ key, const float* __restrict__ value,
       const float* __restrict__ proj){
  extern __shared__ char raw[];
  SP& sm = *reinterpret_cast<SP*>(raw);
  int g = blockIdx.y, split = blockIdx.x;
  int c = g>>5, b = (g>>3)&3, h = g&7;
  int tid = threadIdx.x, lane = tid&31, w = tid>>5;
  int gg = lane>>2, t = lane&3;

  for (int idx = tid; idx < 128*64; idx += 256){
    int m = idx>>6, e = idx&63;
    float x = proj[((size_t)c*MF+m)*ED+e];
    __half hh,ll; split16(x,hh,ll);
    sm.Bp[m][e]=hh; sm.Bp[m][64+e]=hh; sm.Bp[m][128+e]=ll;
  }

  float kvacc[8][4];
  #pragma unroll
  for(int i=0;i<8;i++)
    #pragma unroll
    for(int j=0;j<4;j++) kvacc[i][j]=0.f;
  float kpriv = 0.f;
  float runstab = -CUDART_INF_F;

  for (int tile = 0; tile < 4; tile++){
    int sbase = split*512 + tile*128;
    __syncthreads();
    for (int idx = tid; idx < 128*64; idx += 256){
      int s = idx>>6, e = idx&63;
      size_t gb = (((size_t)b*SEQ + sbase + s)*NHk + h)*ED + e;
      float x = key[gb];
      __half hh,ll; split16(x,hh,ll);
      sm.u.Ak[s][e]=hh; sm.u.Ak[s][64+e]=ll; sm.u.Ak[s][128+e]=hh;
      sm.vT[e][s] = __float2half_rn(value[gb]);
    }
    __syncthreads();
    if (tid < 128){
      float s = 0.f;
      #pragma unroll
      for (int e = 0; e < 64; e++){
        float x = __half2float(sm.u.Ak[tid][e]) + __half2float(sm.u.Ak[tid][64+e]);
        s += x*x;
      }
      sm.snorm[tid] = 0.5f*s;
    }
    __syncthreads();

    int r0 = w*16+gg, r1 = r0+8;
    float n0v = sm.snorm[r0], n1v = sm.snorm[r1];
    float mx = -CUDART_INF_F;
    for (int nh = 0; nh < 2; nh++){
      float c1[8][4];
      #pragma unroll
      for(int i=0;i<8;i++)
        #pragma unroll
        for(int j=0;j<4;j++) c1[i][j]=0.f;
      #pragma unroll
      for (int ks = 0; ks < 12; ks++){
        int k0 = ks*16;
        unsigned a0 = ldu(&sm.u.Ak[r0][k0+2*t]);
        unsigned a1 = ldu(&sm.u.Ak[r1][k0+2*t]);
        unsigned a2 = ldu(&sm.u.Ak[r0][k0+2*t+8]);
        unsigned a3 = ldu(&sm.u.Ak[r1][k0+2*t+8]);
        #pragma unroll
        for (int nt = 0; nt < 8; nt++){
          const __half* br = sm.Bp[nh*64 + nt*8 + gg];
          mma16816(c1[nt], a0,a1,a2,a3, ldu(&br[k0+2*t]), ldu(&br[k0+2*t+8]));
        }
      }
      #pragma unroll
      for (int nt = 0; nt < 8; nt++){
        int col = nh*64 + nt*8 + 2*t;
        float v0=c1[nt][0]-n0v, v1=c1[nt][1]-n0v, v2=c1[nt][2]-n1v, v3=c1[nt][3]-n1v;
        sm.logkS[r0][col]=v0; sm.logkS[r0][col+1]=v1;
        sm.logkS[r1][col]=v2; sm.logkS[r1][col+1]=v3;
        mx = fmaxf(mx, fmaxf(fmaxf(v0,v1),fmaxf(v2,v3)));
      }
    }
    #pragma unroll
    for (int o=16;o>0;o>>=1) mx = fmaxf(mx, __shfl_xor_sync(0xffffffffu,mx,o));
    if (lane==0) sm.wred[w] = mx;
    __syncthreads();
    float tstab = sm.wred[0];
    #pragma unroll
    for (int q=1;q<8;q++) tstab = fmaxf(tstab, sm.wred[q]);
    if (tid==0) g_tstab[g*32 + split*4 + tile] = tstab;
    float newstab = fmaxf(runstab, tstab);
    float fo = expf(runstab - newstab);
    float fn = expf(tstab - newstab);
    runstab = newstab;

    // phi = exp(logk - tstab) -> global fp16 + phiA[m][s]
    float part = 0.f;
    #pragma unroll
    for (int kk = 0; kk < 64; kk++){
      int idx = tid + kk*256;
      int s = idx>>7, m = idx&127;
      float ev = expf(sm.logkS[s][m] - tstab);
      __half hh = __float2half_rn(ev);
      g_phikh[((size_t)g*SEQ + sbase + s)*MF + m] = hh;
      sm.u.phiA[m][s] = hh;
      part += __half2float(hh);
    }
    kpriv = kpriv*fo + fn*part;
    __syncthreads();

    // kv mma: phiA(128m x 128s) x vT(64e x 128s)
    float tmp[8][4];
    #pragma unroll
    for(int i=0;i<8;i++)
      #pragma unroll
      for(int j=0;j<4;j++) tmp[i][j]=0.f;
    #pragma unroll
    for (int ks = 0; ks < 8; ks++){
      int k0 = ks*16;
      unsigned a0 = ldu(&sm.u.phiA[w*16+gg][k0+2*t]);
      unsigned a1 = ldu(&sm.u.phiA[w*16+gg+8][k0+2*t]);
      unsigned a2 = ldu(&sm.u.phiA[w*16+gg][k0+2*t+8]);
      unsigned a3 = ldu(&sm.u.phiA[w*16+gg+8][k0+2*t+8]);
      #pragma unroll
      for (int nt = 0; nt < 8; nt++){
        const __half* br = sm.vT[nt*8+gg];
        mma16816(tmp[nt], a0,a1,a2,a3, ldu(&br[k0+2*t]), ldu(&br[k0+2*t+8]));
      }
    }
    #pragma unroll
    for(int i=0;i<8;i++)
      #pragma unroll
      for(int j=0;j<4;j++) kvacc[i][j] = kvacc[i][j]*fo + tmp[i][j]*fn;
  }

  size_t pb = ((size_t)g*8 + split)*(MF*ED);
  int m0 = w*16+gg, m1 = m0+8;
  #pragma unroll
  for (int nt = 0; nt < 8; nt++){
    int e0 = nt*8 + 2*t;
    *(float2*)&g_kvp[pb + (size_t)m0*64 + e0] = make_float2(kvacc[nt][0], kvacc[nt][1]);
    *(float2*)&g_kvp[pb + (size_t)m1*64 + e0] = make_float2(kvacc[nt][2], kvacc[nt][3]);
  }
  sm.ks2[tid] = kpriv;
  __syncthreads();
  if (tid < 128) g_ksump[((size_t)g*8 + split)*128 + tid] = sm.ks2[tid] + sm.ks2[tid+128];
  if (tid == 0) g_pstab[g*8 + split] = runstab;
}

// ======== K2: global stab ========
__global__ void k_stab(){
  int g = blockIdx.x, lane = threadIdx.x;
  float v = g_tstab[g*32 + lane];
  #pragma unroll
  for (int o=16;o>0;o>>=1) v = fmaxf(v, __shfl_xor_sync(0xffffffffu,v,o));
  if (lane==0) g_stabk[g] = v;
}

// ======== K3: reduce kv/ksum partials with rescale ========
__global__ void k_kvred(){
  int i = blockIdx.x*blockDim.x + threadIdx.x;
  if (i < NG*MF*ED){
    int g = i>>13, me = i&8191;
    float stabg = g_stabk[g], s = 0.f;
    #pragma unroll
    for (int p=0;p<8;p++)
      s += g_kvp[((size_t)g*8+p)*(MF*ED)+me] * expf(g_pstab[g*8+p]-stabg);
    g_kv[i] = s;
  }
}
__global__ void k_ksumred(){
  int i = blockIdx.x*blockDim.x + threadIdx.x;
  if (i < NG*MF){
    int g = i>>7, m = i&127;
    float stabg = g_stabk[g], s = 0.f;
    #pragma unroll
    for (int p=0;p<8;p++)
      s += g_ksump[(g*8+p)*MF+m] * expf(g_pstab[g*8+p]-stabg);
    g_ksum[i] = s;
  }
}

// ======== K4: phi_q, pls, lr_v, lr_1 ========
struct S3 {
  union {
    struct { float sqT[ED][129]; float spT[ED][129]; } in;
    float phiT[MF][132];
  } u;
  float kv[MF][ED+1];
  float snorm[128];
  float rmax[128][17];
  float stabq[128];
  float ksum[MF];
};

__global__ void k_phiq(const float* __restrict__ query, const float* __restrict__ proj){
  extern __shared__ char raw[];
  S3& sm = *reinterpret_cast<S3*>(raw);
  int g = blockIdx.y;
  int c = g>>5, b = (g>>3)&3, h = g&7;
  int q0 = blockIdx.x*128;
  int tid = threadIdx.x;

  for (int idx = tid; idx < 128*ED; idx += 256){
    int i = idx>>6, e = idx&63;
    sm.u.in.sqT[e][i] = query[(((size_t)b*TT + (c*CHQ+q0+i))*NHk + h)*ED + e];
  }
  for (int idx = tid; idx < MF*ED; idx += 256){
    int m = idx>>6, e = idx&63;
    sm.u.in.spT[e][m] = proj[((size_t)c*MF+m)*ED+e];
  }
  for (int idx = tid; idx < MF*ED; idx += 256)
    sm.kv[idx>>6][idx&63] = g_kv[(size_t)g*MF*ED + idx];
  if (tid < MF) sm.ksum[tid] = g_ksum[g*MF+tid];
  __syncthreads();
  if (tid < 128){
    float s = 0.f;
    #pragma unroll
    for (int e=0;e<ED;e++){ float v = sm.u.in.sqT[e][tid]; s += v*v; }
    sm.snorm[tid] = 0.5f*s;
  }
  __syncthreads();

  int tx = tid&15, ty = tid>>4;
  float acc[8][8];
  #pragma unroll
  for(int r=0;r<8;r++)
    #pragma unroll
    for(int c2=0;c2<8;c2++) acc[r][c2]=0.f;
  for (int e=0;e<ED;e++){
    float a[8], bb[8];
    #pragma unroll
    for(int r=0;r<8;r++) a[r]=sm.u.in.sqT[e][ty+16*r];
    #pragma unroll
    for(int c2=0;c2<8;c2++) bb[c2]=sm.u.in.spT[e][tx+16*c2];
    #pragma unroll
    for(int r=0;r<8;r++)
      #pragma unroll
      for(int c2=0;c2<8;c2++) acc[r][c2]=fmaf(a[r],bb[c2],acc[r][c2]);
  }
  #pragma unroll
  for(int r=0;r<8;r++){
    int i = ty+16*r;
    float nrm = sm.snorm[i], pm = -CUDART_INF_F;
    #pragma unroll
    for(int c2=0;c2<8;c2++){ acc[r][c2]-=nrm; pm=fmaxf(pm,acc[r][c2]); }
    sm.rmax[i][tx] = pm;
  }
  __syncthreads();
  float skv = g_stabk[g];
  if (tid < 128){
    float m2 = sm.rmax[tid][0];
    #pragma unroll
    for(int j=1;j<16;j++) m2 = fmaxf(m2, sm.rmax[tid][j]);
    sm.stabq[tid] = m2;
    g_pls[(size_t)g*CHQ + q0 + tid] = m2 + skv - LOGM;
  }
  __syncthreads();
  #pragma unroll
  for(int r=0;r<8;r++){
    int i = ty+16*r;
    float st = sm.stabq[i];
    size_t ro = ((size_t)g*CHQ + q0 + i)*MF;
    #pragma unroll
    for(int c2=0;c2<8;c2++){
      float pv = expf(acc[r][c2]-st);
      int m = tx+16*c2;
      g_phiq[ro+m] = pv;
      sm.u.phiT[m][i] = pv;
    }
  }
  __syncthreads();

  float a2[8][4];
  #pragma unroll
  for(int r=0;r<8;r++)
    #pragma unroll
    for(int cc=0;cc<4;cc++) a2[r][cc]=0.f;
  for (int m=0;m<MF;m++){
    float av[8], bv[4];
    #pragma unroll
    for(int r=0;r<8;r++) av[r]=sm.u.phiT[m][ty+16*r];
    #pragma unroll
    for(int cc=0;cc<4;cc++) bv[cc]=sm.kv[m][tx+16*cc];
    #pragma unroll
    for(int r=0;r<8;r++)
      #pragma unroll
      for(int cc=0;cc<4;cc++) a2[r][cc]=fmaf(av[r],bv[cc],a2[r][cc]);
  }
  #pragma unroll
  for(int r=0;r<8;r++){
    int i = ty+16*r;
    size_t ro = ((size_t)g*CHQ + q0 + i)*ED;
    #pragma unroll
    for(int cc=0;cc<4;cc++) g_lrv[ro + tx + 16*cc] = a2[r][cc];
  }
  if (tid < 128){
    float s = 0.f;
    for (int m=0;m<MF;m++) s = fmaf(sm.u.phiT[m][tid], sm.ksum[m], s);
    g_lr1[(size_t)g*CHQ + q0 + tid] = s;
  }
}

// ======== K5: local windows (64-key band) ========
struct S5 {
  float qT[64][33];
  float k3T[64][65];
  float v3[64][65];
  float pqT[128][33];
  float pk3T[128][65];
  float sc[32][66];
  float dp[32][66];
  float jscale[64];
  float lnorm[32];
  float scl[32];
};

__global__ void __launch_bounds__(256)
k_local(const float* __restrict__ query, const float* __restrict__ key,
        const float* __restrict__ value, float* __restrict__ out){
  extern __shared__ char raw[];
  S5& sm = *reinterpret_cast<S5*>(raw);
  int g = blockIdx.y, n = blockIdx.x;
  int c = g>>5, b = (g>>3)&3, h = g&7;
  int tid = threadIdx.x, lane = tid&31, wrp = tid>>5;
  int t0 = n*32, p0 = t0 - 16;
  float stabg = g_stabk[g];

  if (tid < 64){
    int pos = p0 + tid;
    sm.jscale[tid] = (pos >= 0) ? expf(g_tstab[g*32 + (pos>>7)] - stabg) : 0.f;
  }
  for (int idx = tid; idx < 32*64; idx += 256){
    int qi = idx>>6, e = idx&63;
    sm.qT[e][qi] = query[(((size_t)b*TT + (c*CHQ+t0+qi))*NHk + h)*ED + e];
  }
  for (int idx = tid; idx < 64*64; idx += 256){
    int j = idx>>6, e = idx&63;
    int pos = p0 + j;
    float kx = 0.f, vx = 0.f;
    if (pos >= 0){
      size_t base = (((size_t)b*SEQ + pos)*NHk + h)*ED + e;
      kx = key[base]; vx = value[base];
    }
    sm.k3T[e][j] = kx; sm.v3[j][e] = vx;
  }
  for (int idx = tid; idx < 32*MF; idx += 256){
    int qi = idx>>7, m = idx&127;
    sm.pqT[m][qi] = g_phiq[((size_t)g*CHQ + t0 + qi)*MF + m];
  }
  __syncthreads();
  for (int idx = tid; idx < 64*64; idx += 256){
    int j = idx>>6, m2 = idx&63;
    int pos = p0 + j;
    float sc_ = sm.jscale[j];
    float lo = 0.f, hi = 0.f;
    if (pos >= 0){
      __half2 hv = *(const __half2*)&g_phikh[((size_t)g*SEQ + pos)*MF + 2*m2];
      float2 f = __half22float2(hv);
      lo = f.x*sc_; hi = f.y*sc_;
    }
    sm.pk3T[2*m2][j] = lo; sm.pk3T[2*m2+1][j] = hi;
  }
  __syncthreads();

  float s0[4], s1[4], d0[4], d1[4];
  #pragma unroll
  for(int r=0;r<4;r++){ s0[r]=0.f; s1[r]=0.f; d0[r]=0.f; d1[r]=0.f; }
  for (int e=0;e<64;e++){
    float b0 = sm.k3T[e][lane], b1 = sm.k3T[e][lane+32];
    #pragma unroll
    for(int r=0;r<4;r++){
      float a = sm.qT[e][wrp*4+r];
      s0[r]=fmaf(a,b0,s0[r]); s1[r]=fmaf(a,b1,s1[r]);
    }
  }
  for (int m=0;m<MF;m++){
    float b0 = sm.pk3T[m][lane], b1 = sm.pk3T[m][lane+32];
    #pragma unroll
    for(int r=0;r<4;r++){
      float a = sm.pqT[m][wrp*4+r];
      d0[r]=fmaf(a,b0,d0[r]); d1[r]=fmaf(a,b1,d1[r]);
    }
  }
  #pragma unroll
  for(int r=0;r<4;r++){
    int qi = wrp*4+r;
    int j0 = lane, j1 = lane+32;
    bool v0 = (j0>=qi)&&(j0<qi+32)&&(p0+j0>=0);
    bool v1 = (j1>=qi)&&(j1<qi+32)&&(p0+j1>=0);
    sm.sc[qi][j0] = v0 ? s0[r] : -1e24f;
    sm.sc[qi][j1] = v1 ? s1[r] : -1e24f;
    sm.dp[qi][j0] = v0 ? d0[r] : 0.f;
    sm.dp[qi][j1] = v1 ? d1[r] : 0.f;
  }
  __syncthreads();

  #pragma unroll
  for(int r=0;r<4;r++){
    int row = wrp*4+r;
    float v0 = sm.sc[row][lane], v1 = sm.sc[row][lane+32];
    float mx = fmaxf(v0,v1);
    #pragma unroll
    for(int o=16;o>0;o>>=1) mx = fmaxf(mx, __shfl_xor_sync(0xffffffffu,mx,o));
    float se = expf(v0-mx) + expf(v1-mx);
    #pragma unroll
    for(int o=16;o>0;o>>=1) se += __shfl_xor_sync(0xffffffffu,se,o);
    float lse = mx + logf(se);
    float ds = sm.dp[row][lane] + sm.dp[row][lane+32];
    #pragma unroll
    for(int o=16;o>0;o>>=1) ds += __shfl_xor_sync(0xffffffffu,ds,o);
    float lr1v = g_lr1[(size_t)g*CHQ + t0 + row];
    float plsv = g_pls[(size_t)g*CHQ + t0 + row];
    float rem = fmaxf(lr1v - ds, 1e-24f);
    float bq = logf(rem) + plsv;
    float hi = fmaxf(lse,bq), lo2 = fminf(lse,bq);
    float ln = hi + log1pf(expf(lo2-hi));
    if (lane==0){ sm.lnorm[row]=ln; sm.scl[row]=expf(plsv-ln); }
  }
  __syncthreads();
  for (int idx = tid; idx < 32*64; idx += 256){
    int qi = idx>>6, j = idx&63;
    sm.sc[qi][j] = expf(sm.sc[qi][j] - sm.lnorm[qi]);
  }
  __syncthreads();

  float op[4][2], wn[4][2];
  #pragma unroll
  for(int r=0;r<4;r++)
    #pragma unroll
    for(int ee=0;ee<2;ee++){ op[r][ee]=0.f; wn[r][ee]=0.f; }
  for (int j=0;j<64;j++){
    float bv0 = sm.v3[j][lane], bv1 = sm.v3[j][lane+32];
    #pragma unroll
    for(int r=0;r<4;r++){
      float pv = sm.sc[wrp*4+r][j];
      float dv = sm.dp[wrp*4+r][j];
      op[r][0]=fmaf(pv,bv0,op[r][0]); op[r][1]=fmaf(pv,bv1,op[r][1]);
      wn[r][0]=fmaf(dv,bv0,wn[r][0]); wn[r][1]=fmaf(dv,bv1,wn[r][1]);
    }
  }
  #pragma unroll
  for(int r=0;r<4;r++){
    int qi = wrp*4+r;
    float sl = sm.scl[qi];
    size_t lro = ((size_t)g*CHQ + t0 + qi)*ED;
    float lrv0 = g_lrv[lro + lane], lrv1 = g_lrv[lro + lane + 32];
    size_t ob = (((size_t)b*NHk + h)*TT + (c*CHQ + t0 + qi))*ED;
    out[ob + lane]      = op[r][0] + (lrv0 - wn[r][0])*sl;
    out[ob + lane + 32] = op[r][1] + (lrv1 - wn[r][1])*sl;
  }
}

// ---------------- launch ----------------
extern "C" void kernel_launch(void* const* d_in, const int* in_sizes, int n_in,
                              void* d_out, int out_size){
  const float* query = (const float*)d_in[0];
  const float* key   = (const float*)d_in[1];
  const float* value = (const float*)d_in[2];
  const float* proj  = (const float*)d_in[3];
  float* out = (float*)d_out;

  cudaFuncSetAttribute(k_phik, cudaFuncAttributeMaxDynamicSharedMemorySize, (int)sizeof(SP));
  cudaFuncSetAttribute(k_phiq, cudaFuncAttributeMaxDynamicSharedMemorySize, (int)sizeof(S3));
  cudaFuncSetAttribute(k_local,cudaFuncAttributeMaxDynamicSharedMemorySize, (int)sizeof(S5));

  dim3 gp(8, NG);
  k_phik<<<gp, 256, sizeof(SP)>>>(key, value, proj);
  k_stab<<<NG, 32>>>();
  k_kvred<<<(NG*MF*ED+255)/256, 256>>>();
  k_ksumred<<<(NG*MF+255)/256, 256>>>();
  dim3 gq(CHQ/128, NG);
  k_phiq<<<gq, 256, sizeof(S3)>>>(query, proj);
  dim3 g5(32, NG);
  k_local<<<g5, 256, sizeof(S5)>>>(query, key, value, out);
}

// round 5
// speedup vs baseline: 2.1329x; 1.1634x over previous
#include <cuda_runtime.h>
#include <cuda_fp16.h>
#include <math.h>
#include <math_constants.h>

#define SEQ 4096
#define TT  4096
#define CHQ 1024
#define ED  64
#define MF  128
#define NHk 8
#define NG  128
#define LOGM 4.852030263919617f

__device__ __half g_phikh[(size_t)NG*SEQ*MF];
__device__ __half g_phiqh[(size_t)NG*CHQ*MF];
__device__ float  g_tstab[NG*32];
__device__ float  g_pstab[NG*8];
__device__ float  g_stabk[NG];
__device__ float  g_kvp[(size_t)NG*8*MF*ED];
__device__ float  g_kv[NG*MF*ED];
__device__ float  g_ksump[NG*8*MF];
__device__ float  g_ksum[NG*MF];
__device__ float  g_pls[NG*CHQ];
__device__ float  g_lr1[NG*CHQ];
__device__ float  g_lrv[(size_t)NG*CHQ*ED];

__device__ __forceinline__ void mma16816(float* c, unsigned a0,unsigned a1,unsigned a2,unsigned a3,
                                         unsigned b0,unsigned b1){
  asm volatile("mma.sync.aligned.m16n8k16.row.col.f32.f16.f16.f32 "
    "{%0,%1,%2,%3},{%4,%5,%6,%7},{%8,%9},{%0,%1,%2,%3};"
    : "+f"(c[0]),"+f"(c[1]),"+f"(c[2]),"+f"(c[3])
    : "r"(a0),"r"(a1),"r"(a2),"r"(a3),"r"(b0),"r"(b1));
}
__device__ __forceinline__ unsigned ldu(const __half* p){ return *(const unsigned*)p; }
__device__ __forceinline__ void split16(float x, __half& h, __half& l){
  h = __float2half_rn(x); l = __float2half_rn(x - __half2float(h));
}

// ======== K1: fused logk mma + phi_k(fp16) + kv mma + ksum (per-tile stabs) ====
struct SP {
  __half Bp[128][200];
  union { __half Ak[128][200]; __half phiA[128][136]; } u;
  float logkS[128][132];
  __half vT[64][136];
  float snorm[128];
  float wred[8];
  float ks2[256];
};

__global__ void __launch_bounds__(256,1)
k_phik(const float* __restrict__ key, const float* __restrict__ value,
       const float* __restrict__ proj){
  extern __shared__ char raw[];
  SP& sm = *reinterpret_cast<SP*>(raw);
  int g = blockIdx.y, split = blockIdx.x;
  int c = g>>5, b = (g>>3)&3, h = g&7;
  int tid = threadIdx.x, lane = tid&31, w = tid>>5;
  int gg = lane>>2, t = lane&3;

  for (int idx = tid; idx < 128*64; idx += 256){
    int m = idx>>6, e = idx&63;
    float x = proj[((size_t)c*MF+m)*ED+e];
    __half hh,ll; split16(x,hh,ll);
    sm.Bp[m][e]=hh; sm.Bp[m][64+e]=hh; sm.Bp[m][128+e]=ll;
  }

  float kvacc[8][4];
  #pragma unroll
  for(int i=0;i<8;i++)
    #pragma unroll
    for(int j=0;j<4;j++) kvacc[i][j]=0.f;
  float kpriv = 0.f;
  float runstab = -CUDART_INF_F;

  for (int tile = 0; tile < 4; tile++){
    int sbase = split*512 + tile*128;
    __syncthreads();
    for (int idx = tid; idx < 128*64; idx += 256){
      int s = idx>>6, e = idx&63;
      size_t gb = (((size_t)b*SEQ + sbase + s)*NHk + h)*ED + e;
      float x = key[gb];
      __half hh,ll; split16(x,hh,ll);
      sm.u.Ak[s][e]=hh; sm.u.Ak[s][64+e]=ll; sm.u.Ak[s][128+e]=hh;
      sm.vT[e][s] = __float2half_rn(value[gb]);
    }
    __syncthreads();
    if (tid < 128){
      float s = 0.f;
      #pragma unroll
      for (int e = 0; e < 64; e++){
        float x = __half2float(sm.u.Ak[tid][e]) + __half2float(sm.u.Ak[tid][64+e]);
        s += x*x;
      }
      sm.snorm[tid] = 0.5f*s;
    }
    __syncthreads();

    int r0 = w*16+gg, r1 = r0+8;
    float n0v = sm.snorm[r0], n1v = sm.snorm[r1];
    float mx = -CUDART_INF_F;
    for (int nh = 0; nh < 2; nh++){
      float c1[8][4];
      #pragma unroll
      for(int i=0;i<8;i++)
        #pragma unroll
        for(int j=0;j<4;j++) c1[i][j]=0.f;
      #pragma unroll
      for (int ks = 0; ks < 12; ks++){
        int k0 = ks*16;
        unsigned a0 = ldu(&sm.u.Ak[r0][k0+2*t]);
        unsigned a1 = ldu(&sm.u.Ak[r1][k0+2*t]);
        unsigned a2 = ldu(&sm.u.Ak[r0][k0+2*t+8]);
        unsigned a3 = ldu(&sm.u.Ak[r1][k0+2*t+8]);
        #pragma unroll
        for (int nt = 0; nt < 8; nt++){
          const __half* br = sm.Bp[nh*64 + nt*8 + gg];
          mma16816(c1[nt], a0,a1,a2,a3, ldu(&br[k0+2*t]), ldu(&br[k0+2*t+8]));
        }
      }
      #pragma unroll
      for (int nt = 0; nt < 8; nt++){
        int col = nh*64 + nt*8 + 2*t;
        float v0=c1[nt][0]-n0v, v1=c1[nt][1]-n0v, v2=c1[nt][2]-n1v, v3=c1[nt][3]-n1v;
        sm.logkS[r0][col]=v0; sm.logkS[r0][col+1]=v1;
        sm.logkS[r1][col]=v2; sm.logkS[r1][col+1]=v3;
        mx = fmaxf(mx, fmaxf(fmaxf(v0,v1),fmaxf(v2,v3)));
      }
    }
    #pragma unroll
    for (int o=16;o>0;o>>=1) mx = fmaxf(mx, __shfl_xor_sync(0xffffffffu,mx,o));
    if (lane==0) sm.wred[w] = mx;
    __syncthreads();
    float tstab = sm.wred[0];
    #pragma unroll
    for (int q=1;q<8;q++) tstab = fmaxf(tstab, sm.wred[q]);
    if (tid==0) g_tstab[g*32 + split*4 + tile] = tstab;
    float newstab = fmaxf(runstab, tstab);
    float fo = expf(runstab - newstab);
    float fn = expf(tstab - newstab);
    runstab = newstab;

    float part = 0.f;
    #pragma unroll
    for (int kk = 0; kk < 64; kk++){
      int idx = tid + kk*256;
      int s = idx>>7, m = idx&127;
      float ev = expf(sm.logkS[s][m] - tstab);
      __half hh = __float2half_rn(ev);
      g_phikh[((size_t)g*SEQ + sbase + s)*MF + m] = hh;
      sm.u.phiA[m][s] = hh;
      part += __half2float(hh);
    }
    kpriv = kpriv*fo + fn*part;
    __syncthreads();

    float tmp[8][4];
    #pragma unroll
    for(int i=0;i<8;i++)
      #pragma unroll
      for(int j=0;j<4;j++) tmp[i][j]=0.f;
    #pragma unroll
    for (int ks = 0; ks < 8; ks++){
      int k0 = ks*16;
      unsigned a0 = ldu(&sm.u.phiA[w*16+gg][k0+2*t]);
      unsigned a1 = ldu(&sm.u.phiA[w*16+gg+8][k0+2*t]);
      unsigned a2 = ldu(&sm.u.phiA[w*16+gg][k0+2*t+8]);
      unsigned a3 = ldu(&sm.u.phiA[w*16+gg+8][k0+2*t+8]);
      #pragma unroll
      for (int nt = 0; nt < 8; nt++){
        const __half* br = sm.vT[nt*8+gg];
        mma16816(tmp[nt], a0,a1,a2,a3, ldu(&br[k0+2*t]), ldu(&br[k0+2*t+8]));
      }
    }
    #pragma unroll
    for(int i=0;i<8;i++)
      #pragma unroll
      for(int j=0;j<4;j++) kvacc[i][j] = kvacc[i][j]*fo + tmp[i][j]*fn;
  }

  size_t pb = ((size_t)g*8 + split)*(MF*ED);
  int m0 = w*16+gg, m1 = m0+8;
  #pragma unroll
  for (int nt = 0; nt < 8; nt++){
    int e0 = nt*8 + 2*t;
    *(float2*)&g_kvp[pb + (size_t)m0*64 + e0] = make_float2(kvacc[nt][0], kvacc[nt][1]);
    *(float2*)&g_kvp[pb + (size_t)m1*64 + e0] = make_float2(kvacc[nt][2], kvacc[nt][3]);
  }
  sm.ks2[tid] = kpriv;
  __syncthreads();
  if (tid < 128) g_ksump[((size_t)g*8 + split)*128 + tid] = sm.ks2[tid] + sm.ks2[tid+128];
  if (tid == 0) g_pstab[g*8 + split] = runstab;
}

// ======== K2/K3: stab + partial reductions ========
__global__ void k_stab(){
  int g = blockIdx.x, lane = threadIdx.x;
  float v = g_tstab[g*32 + lane];
  #pragma unroll
  for (int o=16;o>0;o>>=1) v = fmaxf(v, __shfl_xor_sync(0xffffffffu,v,o));
  if (lane==0) g_stabk[g] = v;
}
__global__ void k_kvred(){
  int i = blockIdx.x*blockDim.x + threadIdx.x;
  if (i < NG*MF*ED){
    int g = i>>13, me = i&8191;
    float stabg = g_stabk[g], s = 0.f;
    #pragma unroll
    for (int p=0;p<8;p++)
      s += g_kvp[((size_t)g*8+p)*(MF*ED)+me] * expf(g_pstab[g*8+p]-stabg);
    g_kv[i] = s;
  }
}
__global__ void k_ksumred(){
  int i = blockIdx.x*blockDim.x + threadIdx.x;
  if (i < NG*MF){
    int g = i>>7, m = i&127;
    float stabg = g_stabk[g], s = 0.f;
    #pragma unroll
    for (int p=0;p<8;p++)
      s += g_ksump[(g*8+p)*MF+m] * expf(g_pstab[g*8+p]-stabg);
    g_ksum[i] = s;
  }
}

// ======== K4: phi_q (mma), pls, lr_v (mma), lr_1 ========
struct SQ {
  __half Bp[128][200];
  union { __half Aq[128][200]; __half phiA[128][136]; } u;
  __half kvTh[64][136];
  __half kvTl[64][136];
  float snorm[128];
  float ksum[128];
};

__global__ void __launch_bounds__(256,1)
k_phiq(const float* __restrict__ query, const float* __restrict__ proj){
  extern __shared__ char raw[];
  SQ& sm = *reinterpret_cast<SQ*>(raw);
  int g = blockIdx.y;
  int c = g>>5, b = (g>>3)&3, h = g&7;
  int q0 = blockIdx.x*128;
  int tid = threadIdx.x, lane = tid&31, w = tid>>5;
  int gg = lane>>2, t = lane&3;

  for (int idx = tid; idx < 128*64; idx += 256){
    int m = idx>>6, e = idx&63;
    float x = proj[((size_t)c*MF+m)*ED+e];
    __half hh,ll; split16(x,hh,ll);
    sm.Bp[m][e]=hh; sm.Bp[m][64+e]=hh; sm.Bp[m][128+e]=ll;
  }
  for (int idx = tid; idx < 128*64; idx += 256){
    int i = idx>>6, e = idx&63;
    float x = query[(((size_t)b*TT + (c*CHQ+q0+i))*NHk + h)*ED + e];
    __half hh,ll; split16(x,hh,ll);
    sm.u.Aq[i][e]=hh; sm.u.Aq[i][64+e]=ll; sm.u.Aq[i][128+e]=hh;
  }
  for (int idx = tid; idx < 128*64; idx += 256){
    int m = idx>>6, e = idx&63;
    float x = g_kv[(size_t)g*MF*ED + m*64 + e];
    __half hh,ll; split16(x,hh,ll);
    sm.kvTh[e][m]=hh; sm.kvTl[e][m]=ll;
  }
  if (tid < 128) sm.ksum[tid] = g_ksum[g*MF+tid];
  __syncthreads();
  if (tid < 128){
    float s = 0.f;
    #pragma unroll
    for (int e = 0; e < 64; e++){
      float x = __half2float(sm.u.Aq[tid][e]) + __half2float(sm.u.Aq[tid][64+e]);
      s += x*x;
    }
    sm.snorm[tid] = 0.5f*s;
  }
  __syncthreads();

  int r0 = w*16+gg, r1 = r0+8;
  float fr[2][8][4];
  #pragma unroll
  for(int nh=0;nh<2;nh++)
    #pragma unroll
    for(int i=0;i<8;i++)
      #pragma unroll
      for(int j=0;j<4;j++) fr[nh][i][j]=0.f;
  #pragma unroll
  for (int ks = 0; ks < 12; ks++){
    int k0 = ks*16;
    unsigned a0 = ldu(&sm.u.Aq[r0][k0+2*t]);
    unsigned a1 = ldu(&sm.u.Aq[r1][k0+2*t]);
    unsigned a2 = ldu(&sm.u.Aq[r0][k0+2*t+8]);
    unsigned a3 = ldu(&sm.u.Aq[r1][k0+2*t+8]);
    #pragma unroll
    for(int nh=0;nh<2;nh++)
      #pragma unroll
      for (int nt = 0; nt < 8; nt++){
        const __half* br = sm.Bp[nh*64 + nt*8 + gg];
        mma16816(fr[nh][nt], a0,a1,a2,a3, ldu(&br[k0+2*t]), ldu(&br[k0+2*t+8]));
      }
  }
  float n0v = sm.snorm[r0], n1v = sm.snorm[r1];
  float m0 = -CUDART_INF_F, m1 = -CUDART_INF_F;
  #pragma unroll
  for(int nh=0;nh<2;nh++)
    #pragma unroll
    for(int nt=0;nt<8;nt++){
      fr[nh][nt][0]-=n0v; fr[nh][nt][1]-=n0v; fr[nh][nt][2]-=n1v; fr[nh][nt][3]-=n1v;
      m0 = fmaxf(m0, fmaxf(fr[nh][nt][0], fr[nh][nt][1]));
      m1 = fmaxf(m1, fmaxf(fr[nh][nt][2], fr[nh][nt][3]));
    }
  #pragma unroll
  for (int o=1;o<=2;o<<=1){
    m0 = fmaxf(m0, __shfl_xor_sync(0xffffffffu,m0,o));
    m1 = fmaxf(m1, __shfl_xor_sync(0xffffffffu,m1,o));
  }
  float skv = g_stabk[g];
  if (t == 0){
    g_pls[(size_t)g*CHQ + q0 + r0] = m0 + skv - LOGM;
    g_pls[(size_t)g*CHQ + q0 + r1] = m1 + skv - LOGM;
  }
  __syncthreads();   // Aq reads complete -> phiA overlay safe
  #pragma unroll
  for(int nh=0;nh<2;nh++)
    #pragma unroll
    for(int nt=0;nt<8;nt++){
      int col = nh*64 + nt*8 + 2*t;
      __half h0 = __float2half_rn(expf(fr[nh][nt][0]-m0));
      __half h1 = __float2half_rn(expf(fr[nh][nt][1]-m0));
      __half h2 = __float2half_rn(expf(fr[nh][nt][2]-m1));
      __half h3 = __float2half_rn(expf(fr[nh][nt][3]-m1));
      sm.u.phiA[r0][col]=h0; sm.u.phiA[r0][col+1]=h1;
      sm.u.phiA[r1][col]=h2; sm.u.phiA[r1][col+1]=h3;
      *(__half2*)&g_phiqh[((size_t)g*CHQ+q0+r0)*MF+col] = __halves2half2(h0,h1);
      *(__half2*)&g_phiqh[((size_t)g*CHQ+q0+r1)*MF+col] = __halves2half2(h2,h3);
    }
  __syncthreads();

  // lr_v = phi(128xMF) x kv  (split B, two passes)
  float acc[8][4];
  #pragma unroll
  for(int i=0;i<8;i++)
    #pragma unroll
    for(int j=0;j<4;j++) acc[i][j]=0.f;
  #pragma unroll
  for (int pass=0; pass<2; pass++){
    #pragma unroll
    for (int ks = 0; ks < 8; ks++){
      int k0 = ks*16;
      unsigned a0 = ldu(&sm.u.phiA[r0][k0+2*t]);
      unsigned a1 = ldu(&sm.u.phiA[r1][k0+2*t]);
      unsigned a2 = ldu(&sm.u.phiA[r0][k0+2*t+8]);
      unsigned a3 = ldu(&sm.u.phiA[r1][k0+2*t+8]);
      #pragma unroll
      for (int nt = 0; nt < 8; nt++){
        const __half* br = pass ? sm.kvTl[nt*8+gg] : sm.kvTh[nt*8+gg];
        mma16816(acc[nt], a0,a1,a2,a3, ldu(&br[k0+2*t]), ldu(&br[k0+2*t+8]));
      }
    }
  }
  size_t ro0 = ((size_t)g*CHQ + q0 + r0)*ED;
  size_t ro1 = ((size_t)g*CHQ + q0 + r1)*ED;
  #pragma unroll
  for (int nt = 0; nt < 8; nt++){
    int e0 = nt*8 + 2*t;
    *(float2*)&g_lrv[ro0 + e0] = make_float2(acc[nt][0], acc[nt][1]);
    *(float2*)&g_lrv[ro1 + e0] = make_float2(acc[nt][2], acc[nt][3]);
  }
  if (tid < 128){
    const __half2* p2 = (const __half2*)&sm.u.phiA[tid][0];
    float s = 0.f;
    #pragma unroll
    for (int i = 0; i < 64; i++){
      float2 f = __half22float2(p2[i]);
      s += f.x*sm.ksum[2*i] + f.y*sm.ksum[2*i+1];
    }
    g_lr1[(size_t)g*CHQ + q0 + tid] = s;
  }
}

// ======== K5: local windows via mma ========
struct S5 {
  union { __half A_s[32][200]; __half cA[32][200]; } u;
  __half B_s[64][200];
  __half vT[64][200];
  __half pqA[32][136];
  __half pkB[64][136];
  float sc[32][66];
  float dp[32][66];
  float jscale[64];
  float lnorm[32];
  float scl[32];
};

__global__ void __launch_bounds__(256,2)
k_local(const float* __restrict__ query, const float* __restrict__ key,
        const float* __restrict__ value, float* __restrict__ out){
  extern __shared__ char raw[];
  S5& sm = *reinterpret_cast<S5*>(raw);
  int g = blockIdx.y, n = blockIdx.x;
  int c = g>>5, b = (g>>3)&3, h = g&7;
  int tid = threadIdx.x, lane = tid&31, w = tid>>5;
  int gg = lane>>2, t = lane&3;
  int t0 = n*32, p0 = t0 - 16;
  float stabg = g_stabk[g];

  if (tid < 64){
    int pos = p0 + tid;
    sm.jscale[tid] = (pos >= 0) ? expf(g_tstab[g*32 + (pos>>7)] - stabg) : 0.f;
  }
  for (int idx = tid; idx < 32*64; idx += 256){
    int qi = idx>>6, e = idx&63;
    float x = query[(((size_t)b*TT + (c*CHQ+t0+qi))*NHk + h)*ED + e];
    __half hh,ll; split16(x,hh,ll);
    sm.u.A_s[qi][e]=hh; sm.u.A_s[qi][64+e]=ll; sm.u.A_s[qi][128+e]=hh;
  }
  for (int idx = tid; idx < 64*64; idx += 256){
    int j = idx>>6, e = idx&63;
    int pos = p0 + j;
    float kx = 0.f, vx = 0.f;
    if (pos >= 0){
      size_t base = (((size_t)b*SEQ + pos)*NHk + h)*ED + e;
      kx = key[base]; vx = value[base];
    }
    __half hh,ll; split16(kx,hh,ll);
    sm.B_s[j][e]=hh; sm.B_s[j][64+e]=hh; sm.B_s[j][128+e]=ll;
    __half vh,vl; split16(vx,vh,vl);
    sm.vT[e][j]=vh; sm.vT[e][64+j]=vl; sm.vT[e][128+j]=vh;
  }
  for (int idx = tid; idx < 32*64; idx += 256){
    int qi = idx>>6, mp = idx&63;
    *(unsigned*)&sm.pqA[qi][2*mp] =
      *(const unsigned*)&g_phiqh[((size_t)g*CHQ + t0 + qi)*MF + 2*mp];
  }
  for (int idx = tid; idx < 64*64; idx += 256){
    int j = idx>>6, mp = idx&63;
    int pos = p0 + j;
    unsigned v = 0u;
    if (pos >= 0) v = *(const unsigned*)&g_phikh[((size_t)g*SEQ + pos)*MF + 2*mp];
    *(unsigned*)&sm.pkB[j][2*mp] = v;
  }
  __syncthreads();

  int mt = w&1, ntb = (w>>1)*2;
  int row0 = mt*16+gg, row1 = row0+8;

  // scores mma k=192
  {
    float cs[2][4];
    #pragma unroll
    for(int i=0;i<2;i++)
      #pragma unroll
      for(int j=0;j<4;j++) cs[i][j]=0.f;
    #pragma unroll
    for (int ks = 0; ks < 12; ks++){
      int k0 = ks*16;
      unsigned a0 = ldu(&sm.u.A_s[row0][k0+2*t]);
      unsigned a1 = ldu(&sm.u.A_s[row1][k0+2*t]);
      unsigned a2 = ldu(&sm.u.A_s[row0][k0+2*t+8]);
      unsigned a3 = ldu(&sm.u.A_s[row1][k0+2*t+8]);
      #pragma unroll
      for (int ii = 0; ii < 2; ii++){
        const __half* br = sm.B_s[(ntb+ii)*8+gg];
        mma16816(cs[ii], a0,a1,a2,a3, ldu(&br[k0+2*t]), ldu(&br[k0+2*t+8]));
      }
    }
    #pragma unroll
    for (int ii = 0; ii < 2; ii++){
      int colb = (ntb+ii)*8 + 2*t;
      #pragma unroll
      for (int cc = 0; cc < 2; cc++){
        int j = colb + cc;
        bool ok = (p0 + j >= 0);
        bool v0 = ok && (j>=row0) && (j<row0+32);
        bool v1 = ok && (j>=row1) && (j<row1+32);
        sm.sc[row0][j] = v0 ? cs[ii][cc]   : -1e24f;
        sm.sc[row1][j] = v1 ? cs[ii][2+cc] : -1e24f;
      }
    }
  }
  // dots mma k=128, rescale by jscale post-mma
  {
    float cd[2][4];
    #pragma unroll
    for(int i=0;i<2;i++)
      #pragma unroll
      for(int j=0;j<4;j++) cd[i][j]=0.f;
    #pragma unroll
    for (int ks = 0; ks < 8; ks++){
      int k0 = ks*16;
      unsigned a0 = ldu(&sm.pqA[row0][k0+2*t]);
      unsigned a1 = ldu(&sm.pqA[row1][k0+2*t]);
      unsigned a2 = ldu(&sm.pqA[row0][k0+2*t+8]);
      unsigned a3 = ldu(&sm.pqA[row1][k0+2*t+8]);
      #pragma unroll
      for (int ii = 0; ii < 2; ii++){
        const __half* br = sm.pkB[(ntb+ii)*8+gg];
        mma16816(cd[ii], a0,a1,a2,a3, ldu(&br[k0+2*t]), ldu(&br[k0+2*t+8]));
      }
    }
    #pragma unroll
    for (int ii = 0; ii < 2; ii++){
      int colb = (ntb+ii)*8 + 2*t;
      #pragma unroll
      for (int cc = 0; cc < 2; cc++){
        int j = colb + cc;
        float js = sm.jscale[j];
        bool ok = (p0 + j >= 0);
        bool v0 = ok && (j>=row0) && (j<row0+32);
        bool v1 = ok && (j>=row1) && (j<row1+32);
        sm.dp[row0][j] = v0 ? cd[ii][cc]*js   : 0.f;
        sm.dp[row1][j] = v1 ? cd[ii][2+cc]*js : 0.f;
      }
    }
  }
  __syncthreads();

  #pragma unroll
  for(int r=0;r<4;r++){
    int row = w*4+r;
    float v0 = sm.sc[row][lane], v1 = sm.sc[row][lane+32];
    float mx = fmaxf(v0,v1);
    #pragma unroll
    for(int o=16;o>0;o>>=1) mx = fmaxf(mx, __shfl_xor_sync(0xffffffffu,mx,o));
    float se = expf(v0-mx) + expf(v1-mx);
    #pragma unroll
    for(int o=16;o>0;o>>=1) se += __shfl_xor_sync(0xffffffffu,se,o);
    float lse = mx + logf(se);
    float ds = sm.dp[row][lane] + sm.dp[row][lane+32];
    #pragma unroll
    for(int o=16;o>0;o>>=1) ds += __shfl_xor_sync(0xffffffffu,ds,o);
    float lr1v = g_lr1[(size_t)g*CHQ + t0 + row];
    float plsv = g_pls[(size_t)g*CHQ + t0 + row];
    float rem = fmaxf(lr1v - ds, 1e-24f);
    float bq = logf(rem) + plsv;
    float hi = fmaxf(lse,bq), lo2 = fminf(lse,bq);
    float ln = hi + log1pf(expf(lo2-hi));
    if (lane==0){ sm.lnorm[row]=ln; sm.scl[row]=expf(plsv-ln); }
  }
  __syncthreads();

  // c = p - scl*dp, fp16 split into cA (A_s reuse)
  for (int idx = tid; idx < 32*64; idx += 256){
    int qi = idx>>6, j = idx&63;
    float cv = expf(sm.sc[qi][j] - sm.lnorm[qi]) - sm.scl[qi]*sm.dp[qi][j];
    __half ch, cl; split16(cv, ch, cl);
    sm.u.cA[qi][j]=ch; sm.u.cA[qi][64+j]=ch; sm.u.cA[qi][128+j]=cl;
  }
  __syncthreads();

  // epilogue mma: (32q x 64j) x (64j x 64e), k=192 split
  float ep[2][4];
  #pragma unroll
  for(int i=0;i<2;i++)
    #pragma unroll
    for(int j=0;j<4;j++) ep[i][j]=0.f;
  #pragma unroll
  for (int ks = 0; ks < 12; ks++){
    int k0 = ks*16;
    unsigned a0 = ldu(&sm.u.cA[row0][k0+2*t]);
    unsigned a1 = ldu(&sm.u.cA[row1][k0+2*t]);
    unsigned a2 = ldu(&sm.u.cA[row0][k0+2*t+8]);
    unsigned a3 = ldu(&sm.u.cA[row1][k0+2*t+8]);
    #pragma unroll
    for (int ii = 0; ii < 2; ii++){
      const __half* br = sm.vT[(ntb+ii)*8+gg];
      mma16816(ep[ii], a0,a1,a2,a3, ldu(&br[k0+2*t]), ldu(&br[k0+2*t+8]));
    }
  }
  float sc0 = sm.scl[row0], sc1 = sm.scl[row1];
  size_t lr0 = ((size_t)g*CHQ + t0 + row0)*ED;
  size_t lr1o = ((size_t)g*CHQ + t0 + row1)*ED;
  size_t ob0 = (((size_t)b*NHk + h)*TT + (c*CHQ + t0 + row0))*ED;
  size_t ob1 = (((size_t)b*NHk + h)*TT + (c*CHQ + t0 + row1))*ED;
  #pragma unroll
  for (int ii = 0; ii < 2; ii++){
    int e0 = (ntb+ii)*8 + 2*t;
    float2 l0 = *(const float2*)&g_lrv[lr0 + e0];
    float2 l1 = *(const float2*)&g_lrv[lr1o + e0];
    out[ob0 + e0]   = ep[ii][0] + sc0*l0.x;
    out[ob0 + e0+1] = ep[ii][1] + sc0*l0.y;
    out[ob1 + e0]   = ep[ii][2] + sc1*l1.x;
    out[ob1 + e0+1] = ep[ii][3] + sc1*l1.y;
  }
}

// ---------------- launch ----------------
extern "C" void kernel_launch(void* const* d_in, const int* in_sizes, int n_in,
                              void* d_out, int out_size){
  const float* query = (const float*)d_in[0];
  const float* key   = (const float*)d_in[1];
  const float* value = (const float*)d_in[2];
  const float* proj  = (const float*)d_in[3];
  float* out = (float*)d_out;

  cudaFuncSetAttribute(k_phik, cudaFuncAttributeMaxDynamicSharedMemorySize, (int)sizeof(SP));
  cudaFuncSetAttribute(k_phiq, cudaFuncAttributeMaxDynamicSharedMemorySize, (int)sizeof(SQ));
  cudaFuncSetAttribute(k_local,cudaFuncAttributeMaxDynamicSharedMemorySize, (int)sizeof(S5));

  dim3 gp(8, NG);
  k_phik<<<gp, 256, sizeof(SP)>>>(key, value, proj);
  k_stab<<<NG, 32>>>();
  k_kvred<<<(NG*MF*ED+255)/256, 256>>>();
  k_ksumred<<<(NG*MF+255)/256, 256>>>();
  dim3 gq(CHQ/128, NG);
  k_phiq<<<gq, 256, sizeof(SQ)>>>(query, proj);
  dim3 g5(32, NG);
  k_local<<<g5, 256, sizeof(S5)>>>(query, key, value, out);
}

// round 6
// speedup vs baseline: 2.7284x; 1.2792x over previous
#include <cuda_runtime.h>
#include <cuda_fp16.h>
#include <math.h>
#include <math_constants.h>

#define SEQ 4096
#define TT  4096
#define CHQ 1024
#define ED  64
#define MF  128
#define NHk 8
#define NG  128
#define LOGM 4.852030263919617f

__device__ __half g_phikh[(size_t)NG*SEQ*MF];
__device__ __half g_phiqh[(size_t)NG*CHQ*MF];
__device__ float  g_tstab[NG*32];
__device__ float  g_stabk[NG];
__device__ float  g_kvp[(size_t)NG*32*MF*ED];     // per-tile partials
__device__ float  g_kv[NG*MF*ED];
__device__ float  g_ksump[NG*32*MF];
__device__ float  g_ksum[NG*MF];
__device__ float  g_pls[NG*CHQ];
__device__ float  g_lr1[NG*CHQ];
__device__ float  g_lrv[(size_t)NG*CHQ*ED];

__device__ __forceinline__ void mma16816(float* c, unsigned a0,unsigned a1,unsigned a2,unsigned a3,
                                         unsigned b0,unsigned b1){
  asm volatile("mma.sync.aligned.m16n8k16.row.col.f32.f16.f16.f32 "
    "{%0,%1,%2,%3},{%4,%5,%6,%7},{%8,%9},{%0,%1,%2,%3};"
    : "+f"(c[0]),"+f"(c[1]),"+f"(c[2]),"+f"(c[3])
    : "r"(a0),"r"(a1),"r"(a2),"r"(a3),"r"(b0),"r"(b1));
}
__device__ __forceinline__ unsigned ldu(const __half* p){ return *(const unsigned*)p; }
__device__ __forceinline__ void split16(float x, __half& h, __half& l){
  h = __float2half_rn(x); l = __float2half_rn(x - __half2float(h));
}

// 3-term split slices: (a_off, b_off) pairs over [hi|lo] 128-wide layouts
__constant__ int c_ao[3] = {0, 64, 0};
__constant__ int c_bo[3] = {0, 0, 64};

// ======== K1: fused logk mma + phi_k(fp16) + kv mma + ksum, per-tile partials ====
struct SP {
  __half Bp[128][136];                               // proj [ph|pl]
  union { __half Ak[128][136]; __half phiA[128][136]; } u;  // key [kh|kl] / phi[m][s]
  __half vT[64][136];
  float snorm[128];
  float wred[8];
};

__global__ void __launch_bounds__(256,2)
k_phik(const float* __restrict__ key, const float* __restrict__ value,
       const float* __restrict__ proj){
  extern __shared__ char raw[];
  SP& sm = *reinterpret_cast<SP*>(raw);
  int g = blockIdx.y, split = blockIdx.x;
  int c = g>>5, b = (g>>3)&3, h = g&7;
  int tid = threadIdx.x, lane = tid&31, w = tid>>5;
  int gg = lane>>2, t = lane&3;

  for (int idx = tid; idx < 128*64; idx += 256){
    int m = idx>>6, e = idx&63;
    float x = proj[((size_t)c*MF+m)*ED+e];
    __half hh,ll; split16(x,hh,ll);
    sm.Bp[m][e]=hh; sm.Bp[m][64+e]=ll;
  }

  for (int tile = 0; tile < 4; tile++){
    int sbase = split*512 + tile*128;
    int tsi = g*32 + split*4 + tile;
    __syncthreads();
    for (int idx = tid; idx < 128*64; idx += 256){
      int s = idx>>6, e = idx&63;
      size_t gb = (((size_t)b*SEQ + sbase + s)*NHk + h)*ED + e;
      float x = key[gb];
      __half hh,ll; split16(x,hh,ll);
      sm.u.Ak[s][e]=hh; sm.u.Ak[s][64+e]=ll;
      sm.vT[e][s] = __float2half_rn(value[gb]);
    }
    __syncthreads();
    if (tid < 128){
      float s = 0.f;
      #pragma unroll
      for (int e = 0; e < 64; e++){
        float x = __half2float(sm.u.Ak[tid][e]) + __half2float(sm.u.Ak[tid][64+e]);
        s += x*x;
      }
      sm.snorm[tid] = 0.5f*s;
    }
    __syncthreads();

    int r0 = w*16+gg, r1 = r0+8;
    float fr[2][8][4];
    #pragma unroll
    for(int nh=0;nh<2;nh++)
      #pragma unroll
      for(int i=0;i<8;i++)
        #pragma unroll
        for(int j=0;j<4;j++) fr[nh][i][j]=0.f;
    #pragma unroll
    for (int term = 0; term < 3; term++){
      int ao = c_ao[term], bo = c_bo[term];
      #pragma unroll
      for (int ks = 0; ks < 4; ks++){
        int k0 = ks*16;
        unsigned a0 = ldu(&sm.u.Ak[r0][ao+k0+2*t]);
        unsigned a1 = ldu(&sm.u.Ak[r1][ao+k0+2*t]);
        unsigned a2 = ldu(&sm.u.Ak[r0][ao+k0+2*t+8]);
        unsigned a3 = ldu(&sm.u.Ak[r1][ao+k0+2*t+8]);
        #pragma unroll
        for(int nh=0;nh<2;nh++)
          #pragma unroll
          for (int nt = 0; nt < 8; nt++){
            const __half* br = sm.Bp[nh*64 + nt*8 + gg];
            mma16816(fr[nh][nt], a0,a1,a2,a3, ldu(&br[bo+k0+2*t]), ldu(&br[bo+k0+2*t+8]));
          }
      }
    }
    float n0v = sm.snorm[r0], n1v = sm.snorm[r1];
    float mx = -CUDART_INF_F;
    #pragma unroll
    for(int nh=0;nh<2;nh++)
      #pragma unroll
      for(int nt=0;nt<8;nt++){
        fr[nh][nt][0]-=n0v; fr[nh][nt][1]-=n0v; fr[nh][nt][2]-=n1v; fr[nh][nt][3]-=n1v;
        mx = fmaxf(mx, fmaxf(fmaxf(fr[nh][nt][0],fr[nh][nt][1]),fmaxf(fr[nh][nt][2],fr[nh][nt][3])));
      }
    #pragma unroll
    for (int o=16;o>0;o>>=1) mx = fmaxf(mx, __shfl_xor_sync(0xffffffffu,mx,o));
    if (lane==0) sm.wred[w] = mx;
    __syncthreads();
    float tstab = sm.wred[0];
    #pragma unroll
    for (int q=1;q<8;q++) tstab = fmaxf(tstab, sm.wred[q]);
    if (tid==0) g_tstab[tsi] = tstab;

    // exp on fragments -> global fp16 + phiA[m][s] (overlays Ak; mma1 reads done)
    size_t gr0 = ((size_t)g*SEQ + sbase + r0)*MF;
    size_t gr1 = ((size_t)g*SEQ + sbase + r1)*MF;
    #pragma unroll
    for(int nh=0;nh<2;nh++)
      #pragma unroll
      for(int nt=0;nt<8;nt++){
        int col = nh*64 + nt*8 + 2*t;
        __half h0 = __float2half_rn(__expf(fr[nh][nt][0]-tstab));
        __half h1 = __float2half_rn(__expf(fr[nh][nt][1]-tstab));
        __half h2 = __float2half_rn(__expf(fr[nh][nt][2]-tstab));
        __half h3 = __float2half_rn(__expf(fr[nh][nt][3]-tstab));
        *(__half2*)&g_phikh[gr0+col] = __halves2half2(h0,h1);
        *(__half2*)&g_phikh[gr1+col] = __halves2half2(h2,h3);
        sm.u.phiA[col][r0]=h0; sm.u.phiA[col+1][r0]=h1;
        sm.u.phiA[col][r1]=h2; sm.u.phiA[col+1][r1]=h3;
      }
    __syncthreads();

    if (tid < 128){
      const __half2* p2 = (const __half2*)&sm.u.phiA[tid][0];
      float s = 0.f;
      #pragma unroll
      for (int i = 0; i < 64; i++){ float2 f = __half22float2(p2[i]); s += f.x+f.y; }
      g_ksump[(size_t)tsi*MF + tid] = s;
    }

    // kv mma: phiA(128m x 128s) x vT(64e x 128s) -> per-tile partial
    float tmp[8][4];
    #pragma unroll
    for(int i=0;i<8;i++)
      #pragma unroll
      for(int j=0;j<4;j++) tmp[i][j]=0.f;
    #pragma unroll
    for (int ks = 0; ks < 8; ks++){
      int k0 = ks*16;
      unsigned a0 = ldu(&sm.u.phiA[w*16+gg][k0+2*t]);
      unsigned a1 = ldu(&sm.u.phiA[w*16+gg+8][k0+2*t]);
      unsigned a2 = ldu(&sm.u.phiA[w*16+gg][k0+2*t+8]);
      unsigned a3 = ldu(&sm.u.phiA[w*16+gg+8][k0+2*t+8]);
      #pragma unroll
      for (int nt = 0; nt < 8; nt++){
        const __half* br = sm.vT[nt*8+gg];
        mma16816(tmp[nt], a0,a1,a2,a3, ldu(&br[k0+2*t]), ldu(&br[k0+2*t+8]));
      }
    }
    size_t pb = (size_t)tsi*(MF*ED);
    int m0 = w*16+gg, m1 = m0+8;
    #pragma unroll
    for (int nt = 0; nt < 8; nt++){
      int e0 = nt*8 + 2*t;
      *(float2*)&g_kvp[pb + (size_t)m0*64 + e0] = make_float2(tmp[nt][0], tmp[nt][1]);
      *(float2*)&g_kvp[pb + (size_t)m1*64 + e0] = make_float2(tmp[nt][2], tmp[nt][3]);
    }
  }
}

// ======== K2/K3: stab + reductions (fold per-tile rescale) ========
__global__ void k_stab(){
  int g = blockIdx.x, lane = threadIdx.x;
  float v = g_tstab[g*32 + lane];
  #pragma unroll
  for (int o=16;o>0;o>>=1) v = fmaxf(v, __shfl_xor_sync(0xffffffffu,v,o));
  if (lane==0) g_stabk[g] = v;
}
__global__ void k_kvred(){
  int i = blockIdx.x*blockDim.x + threadIdx.x;
  if (i < NG*MF*ED){
    int g = i>>13, me = i&8191;
    float stabg = g_stabk[g], s = 0.f;
    #pragma unroll
    for (int p=0;p<32;p++)
      s += g_kvp[((size_t)g*32+p)*(MF*ED)+me] * __expf(g_tstab[g*32+p]-stabg);
    g_kv[i] = s;
  }
}
__global__ void k_ksumred(){
  int i = blockIdx.x*blockDim.x + threadIdx.x;
  if (i < NG*MF){
    int g = i>>7, m = i&127;
    float stabg = g_stabk[g], s = 0.f;
    #pragma unroll
    for (int p=0;p<32;p++)
      s += g_ksump[(size_t)(g*32+p)*MF+m] * __expf(g_tstab[g*32+p]-stabg);
    g_ksum[i] = s;
  }
}

// ======== K4: phi_q (mma), pls, lr_v (mma), lr_1 ========
struct SQ {
  __half Bp[128][136];                               // proj [ph|pl]
  union { __half Aq[128][136]; __half phiA[128][136]; } u;  // query [qh|ql] / phi[q][m]
  __half kvTh[64][136];
  __half kvTl[64][136];
  float snorm[128];
  float ksum[128];
};

__global__ void __launch_bounds__(256,2)
k_phiq(const float* __restrict__ query, const float* __restrict__ proj){
  extern __shared__ char raw[];
  SQ& sm = *reinterpret_cast<SQ*>(raw);
  int g = blockIdx.y;
  int c = g>>5, b = (g>>3)&3, h = g&7;
  int q0 = blockIdx.x*128;
  int tid = threadIdx.x, lane = tid&31, w = tid>>5;
  int gg = lane>>2, t = lane&3;

  for (int idx = tid; idx < 128*64; idx += 256){
    int m = idx>>6, e = idx&63;
    float x = proj[((size_t)c*MF+m)*ED+e];
    __half hh,ll; split16(x,hh,ll);
    sm.Bp[m][e]=hh; sm.Bp[m][64+e]=ll;
  }
  for (int idx = tid; idx < 128*64; idx += 256){
    int i = idx>>6, e = idx&63;
    float x = query[(((size_t)b*TT + (c*CHQ+q0+i))*NHk + h)*ED + e];
    __half hh,ll; split16(x,hh,ll);
    sm.u.Aq[i][e]=hh; sm.u.Aq[i][64+e]=ll;
  }
  for (int idx = tid; idx < 128*64; idx += 256){
    int m = idx>>6, e = idx&63;
    float x = g_kv[(size_t)g*MF*ED + m*64 + e];
    __half hh,ll; split16(x,hh,ll);
    sm.kvTh[e][m]=hh; sm.kvTl[e][m]=ll;
  }
  if (tid < 128) sm.ksum[tid] = g_ksum[g*MF+tid];
  __syncthreads();
  if (tid < 128){
    float s = 0.f;
    #pragma unroll
    for (int e = 0; e < 64; e++){
      float x = __half2float(sm.u.Aq[tid][e]) + __half2float(sm.u.Aq[tid][64+e]);
      s += x*x;
    }
    sm.snorm[tid] = 0.5f*s;
  }
  __syncthreads();

  int r0 = w*16+gg, r1 = r0+8;
  float fr[2][8][4];
  #pragma unroll
  for(int nh=0;nh<2;nh++)
    #pragma unroll
    for(int i=0;i<8;i++)
      #pragma unroll
      for(int j=0;j<4;j++) fr[nh][i][j]=0.f;
  #pragma unroll
  for (int term = 0; term < 3; term++){
    int ao = c_ao[term], bo = c_bo[term];
    #pragma unroll
    for (int ks = 0; ks < 4; ks++){
      int k0 = ks*16;
      unsigned a0 = ldu(&sm.u.Aq[r0][ao+k0+2*t]);
      unsigned a1 = ldu(&sm.u.Aq[r1][ao+k0+2*t]);
      unsigned a2 = ldu(&sm.u.Aq[r0][ao+k0+2*t+8]);
      unsigned a3 = ldu(&sm.u.Aq[r1][ao+k0+2*t+8]);
      #pragma unroll
      for(int nh=0;nh<2;nh++)
        #pragma unroll
        for (int nt = 0; nt < 8; nt++){
          const __half* br = sm.Bp[nh*64 + nt*8 + gg];
          mma16816(fr[nh][nt], a0,a1,a2,a3, ldu(&br[bo+k0+2*t]), ldu(&br[bo+k0+2*t+8]));
        }
    }
  }
  float n0v = sm.snorm[r0], n1v = sm.snorm[r1];
  float m0 = -CUDART_INF_F, m1 = -CUDART_INF_F;
  #pragma unroll
  for(int nh=0;nh<2;nh++)
    #pragma unroll
    for(int nt=0;nt<8;nt++){
      fr[nh][nt][0]-=n0v; fr[nh][nt][1]-=n0v; fr[nh][nt][2]-=n1v; fr[nh][nt][3]-=n1v;
      m0 = fmaxf(m0, fmaxf(fr[nh][nt][0], fr[nh][nt][1]));
      m1 = fmaxf(m1, fmaxf(fr[nh][nt][2], fr[nh][nt][3]));
    }
  #pragma unroll
  for (int o=1;o<=2;o<<=1){
    m0 = fmaxf(m0, __shfl_xor_sync(0xffffffffu,m0,o));
    m1 = fmaxf(m1, __shfl_xor_sync(0xffffffffu,m1,o));
  }
  float skv = g_stabk[g];
  if (t == 0){
    g_pls[(size_t)g*CHQ + q0 + r0] = m0 + skv - LOGM;
    g_pls[(size_t)g*CHQ + q0 + r1] = m1 + skv - LOGM;
  }
  __syncthreads();
  size_t gq0 = ((size_t)g*CHQ+q0+r0)*MF;
  size_t gq1 = ((size_t)g*CHQ+q0+r1)*MF;
  #pragma unroll
  for(int nh=0;nh<2;nh++)
    #pragma unroll
    for(int nt=0;nt<8;nt++){
      int col = nh*64 + nt*8 + 2*t;
      __half h0 = __float2half_rn(__expf(fr[nh][nt][0]-m0));
      __half h1 = __float2half_rn(__expf(fr[nh][nt][1]-m0));
      __half h2 = __float2half_rn(__expf(fr[nh][nt][2]-m1));
      __half h3 = __float2half_rn(__expf(fr[nh][nt][3]-m1));
      sm.u.phiA[r0][col]=h0; sm.u.phiA[r0][col+1]=h1;
      sm.u.phiA[r1][col]=h2; sm.u.phiA[r1][col+1]=h3;
      *(__half2*)&g_phiqh[gq0+col] = __halves2half2(h0,h1);
      *(__half2*)&g_phiqh[gq1+col] = __halves2half2(h2,h3);
    }
  __syncthreads();

  float acc[8][4];
  #pragma unroll
  for(int i=0;i<8;i++)
    #pragma unroll
    for(int j=0;j<4;j++) acc[i][j]=0.f;
  #pragma unroll
  for (int pass=0; pass<2; pass++){
    #pragma unroll
    for (int ks = 0; ks < 8; ks++){
      int k0 = ks*16;
      unsigned a0 = ldu(&sm.u.phiA[r0][k0+2*t]);
      unsigned a1 = ldu(&sm.u.phiA[r1][k0+2*t]);
      unsigned a2 = ldu(&sm.u.phiA[r0][k0+2*t+8]);
      unsigned a3 = ldu(&sm.u.phiA[r1][k0+2*t+8]);
      #pragma unroll
      for (int nt = 0; nt < 8; nt++){
        const __half* br = pass ? sm.kvTl[nt*8+gg] : sm.kvTh[nt*8+gg];
        mma16816(acc[nt], a0,a1,a2,a3, ldu(&br[k0+2*t]), ldu(&br[k0+2*t+8]));
      }
    }
  }
  size_t ro0 = ((size_t)g*CHQ + q0 + r0)*ED;
  size_t ro1 = ((size_t)g*CHQ + q0 + r1)*ED;
  #pragma unroll
  for (int nt = 0; nt < 8; nt++){
    int e0 = nt*8 + 2*t;
    *(float2*)&g_lrv[ro0 + e0] = make_float2(acc[nt][0], acc[nt][1]);
    *(float2*)&g_lrv[ro1 + e0] = make_float2(acc[nt][2], acc[nt][3]);
  }
  if (tid < 128){
    const __half2* p2 = (const __half2*)&sm.u.phiA[tid][0];
    float s = 0.f;
    #pragma unroll
    for (int i = 0; i < 64; i++){
      float2 f = __half22float2(p2[i]);
      s += f.x*sm.ksum[2*i] + f.y*sm.ksum[2*i+1];
    }
    g_lr1[(size_t)g*CHQ + q0 + tid] = s;
  }
}

// ======== K5: local windows via mma ========
struct S5 {
  union { __half A_s[32][200]; __half cA[32][200]; } u;
  __half B_s[64][200];
  __half vT[64][200];
  __half pqA[32][136];
  __half pkB[64][136];
  float sc[32][66];
  float dp[32][66];
  float jscale[64];
  float lnorm[32];
  float scl[32];
};

__global__ void __launch_bounds__(256,2)
k_local(const float* __restrict__ query, const float* __restrict__ key,
        const float* __restrict__ value, float* __restrict__ out){
  extern __shared__ char raw[];
  S5& sm = *reinterpret_cast<S5*>(raw);
  int g = blockIdx.y, n = blockIdx.x;
  int c = g>>5, b = (g>>3)&3, h = g&7;
  int tid = threadIdx.x, lane = tid&31, w = tid>>5;
  int gg = lane>>2, t = lane&3;
  int t0 = n*32, p0 = t0 - 16;
  float stabg = g_stabk[g];

  if (tid < 64){
    int pos = p0 + tid;
    sm.jscale[tid] = (pos >= 0) ? __expf(g_tstab[g*32 + (pos>>7)] - stabg) : 0.f;
  }
  for (int idx = tid; idx < 32*64; idx += 256){
    int qi = idx>>6, e = idx&63;
    float x = query[(((size_t)b*TT + (c*CHQ+t0+qi))*NHk + h)*ED + e];
    __half hh,ll; split16(x,hh,ll);
    sm.u.A_s[qi][e]=hh; sm.u.A_s[qi][64+e]=ll; sm.u.A_s[qi][128+e]=hh;
  }
  for (int idx = tid; idx < 64*64; idx += 256){
    int j = idx>>6, e = idx&63;
    int pos = p0 + j;
    float kx = 0.f, vx = 0.f;
    if (pos >= 0){
      size_t base = (((size_t)b*SEQ + pos)*NHk + h)*ED + e;
      kx = key[base]; vx = value[base];
    }
    __half hh,ll; split16(kx,hh,ll);
    sm.B_s[j][e]=hh; sm.B_s[j][64+e]=hh; sm.B_s[j][128+e]=ll;
    __half vh,vl; split16(vx,vh,vl);
    sm.vT[e][j]=vh; sm.vT[e][64+j]=vl; sm.vT[e][128+j]=vh;
  }
  for (int idx = tid; idx < 32*64; idx += 256){
    int qi = idx>>6, mp = idx&63;
    *(unsigned*)&sm.pqA[qi][2*mp] =
      *(const unsigned*)&g_phiqh[((size_t)g*CHQ + t0 + qi)*MF + 2*mp];
  }
  for (int idx = tid; idx < 64*64; idx += 256){
    int j = idx>>6, mp = idx&63;
    int pos = p0 + j;
    unsigned v = 0u;
    if (pos >= 0) v = *(const unsigned*)&g_phikh[((size_t)g*SEQ + pos)*MF + 2*mp];
    *(unsigned*)&sm.pkB[j][2*mp] = v;
  }
  __syncthreads();

  int mt = w&1, ntb = (w>>1)*2;
  int row0 = mt*16+gg, row1 = row0+8;

  {
    float cs[2][4];
    #pragma unroll
    for(int i=0;i<2;i++)
      #pragma unroll
      for(int j=0;j<4;j++) cs[i][j]=0.f;
    #pragma unroll
    for (int ks = 0; ks < 12; ks++){
      int k0 = ks*16;
      unsigned a0 = ldu(&sm.u.A_s[row0][k0+2*t]);
      unsigned a1 = ldu(&sm.u.A_s[row1][k0+2*t]);
      unsigned a2 = ldu(&sm.u.A_s[row0][k0+2*t+8]);
      unsigned a3 = ldu(&sm.u.A_s[row1][k0+2*t+8]);
      #pragma unroll
      for (int ii = 0; ii < 2; ii++){
        const __half* br = sm.B_s[(ntb+ii)*8+gg];
        mma16816(cs[ii], a0,a1,a2,a3, ldu(&br[k0+2*t]), ldu(&br[k0+2*t+8]));
      }
    }
    #pragma unroll
    for (int ii = 0; ii < 2; ii++){
      int colb = (ntb+ii)*8 + 2*t;
      #pragma unroll
      for (int cc = 0; cc < 2; cc++){
        int j = colb + cc;
        bool ok = (p0 + j >= 0);
        bool v0 = ok && (j>=row0) && (j<row0+32);
        bool v1 = ok && (j>=row1) && (j<row1+32);
        sm.sc[row0][j] = v0 ? cs[ii][cc]   : -1e24f;
        sm.sc[row1][j] = v1 ? cs[ii][2+cc] : -1e24f;
      }
    }
  }
  {
    float cd[2][4];
    #pragma unroll
    for(int i=0;i<2;i++)
      #pragma unroll
      for(int j=0;j<4;j++) cd[i][j]=0.f;
    #pragma unroll
    for (int ks = 0; ks < 8; ks++){
      int k0 = ks*16;
      unsigned a0 = ldu(&sm.pqA[row0][k0+2*t]);
      unsigned a1 = ldu(&sm.pqA[row1][k0+2*t]);
      unsigned a2 = ldu(&sm.pqA[row0][k0+2*t+8]);
      unsigned a3 = ldu(&sm.pqA[row1][k0+2*t+8]);
      #pragma unroll
      for (int ii = 0; ii < 2; ii++){
        const __half* br = sm.pkB[(ntb+ii)*8+gg];
        mma16816(cd[ii], a0,a1,a2,a3, ldu(&br[k0+2*t]), ldu(&br[k0+2*t+8]));
      }
    }
    #pragma unroll
    for (int ii = 0; ii < 2; ii++){
      int colb = (ntb+ii)*8 + 2*t;
      #pragma unroll
      for (int cc = 0; cc < 2; cc++){
        int j = colb + cc;
        float js = sm.jscale[j];
        bool ok = (p0 + j >= 0);
        bool v0 = ok && (j>=row0) && (j<row0+32);
        bool v1 = ok && (j>=row1) && (j<row1+32);
        sm.dp[row0][j] = v0 ? cd[ii][cc]*js   : 0.f;
        sm.dp[row1][j] = v1 ? cd[ii][2+cc]*js : 0.f;
      }
    }
  }
  __syncthreads();

  #pragma unroll
  for(int r=0;r<4;r++){
    int row = w*4+r;
    float v0 = sm.sc[row][lane], v1 = sm.sc[row][lane+32];
    float mx = fmaxf(v0,v1);
    #pragma unroll
    for(int o=16;o>0;o>>=1) mx = fmaxf(mx, __shfl_xor_sync(0xffffffffu,mx,o));
    float se = __expf(v0-mx) + __expf(v1-mx);
    #pragma unroll
    for(int o=16;o>0;o>>=1) se += __shfl_xor_sync(0xffffffffu,se,o);
    float lse = mx + logf(se);
    float ds = sm.dp[row][lane] + sm.dp[row][lane+32];
    #pragma unroll
    for(int o=16;o>0;o>>=1) ds += __shfl_xor_sync(0xffffffffu,ds,o);
    float lr1v = g_lr1[(size_t)g*CHQ + t0 + row];
    float plsv = g_pls[(size_t)g*CHQ + t0 + row];
    float rem = fmaxf(lr1v - ds, 1e-24f);
    float bq = logf(rem) + plsv;
    float hi = fmaxf(lse,bq), lo2 = fminf(lse,bq);
    float ln = hi + log1pf(__expf(lo2-hi));
    if (lane==0){ sm.lnorm[row]=ln; sm.scl[row]=__expf(plsv-ln); }
  }
  __syncthreads();

  for (int idx = tid; idx < 32*64; idx += 256){
    int qi = idx>>6, j = idx&63;
    float cv = __expf(sm.sc[qi][j] - sm.lnorm[qi]) - sm.scl[qi]*sm.dp[qi][j];
    __half ch, cl; split16(cv, ch, cl);
    sm.u.cA[qi][j]=ch; sm.u.cA[qi][64+j]=ch; sm.u.cA[qi][128+j]=cl;
  }
  __syncthreads();

  float ep[2][4];
  #pragma unroll
  for(int i=0;i<2;i++)
    #pragma unroll
    for(int j=0;j<4;j++) ep[i][j]=0.f;
  #pragma unroll
  for (int ks = 0; ks < 12; ks++){
    int k0 = ks*16;
    unsigned a0 = ldu(&sm.u.cA[row0][k0+2*t]);
    unsigned a1 = ldu(&sm.u.cA[row1][k0+2*t]);
    unsigned a2 = ldu(&sm.u.cA[row0][k0+2*t+8]);
    unsigned a3 = ldu(&sm.u.cA[row1][k0+2*t+8]);
    #pragma unroll
    for (int ii = 0; ii < 2; ii++){
      const __half* br = sm.vT[(ntb+ii)*8+gg];
      mma16816(ep[ii], a0,a1,a2,a3, ldu(&br[k0+2*t]), ldu(&br[k0+2*t+8]));
    }
  }
  float sc0 = sm.scl[row0], sc1 = sm.scl[row1];
  size_t lr0 = ((size_t)g*CHQ + t0 + row0)*ED;
  size_t lr1o = ((size_t)g*CHQ + t0 + row1)*ED;
  size_t ob0 = (((size_t)b*NHk + h)*TT + (c*CHQ + t0 + row0))*ED;
  size_t ob1 = (((size_t)b*NHk + h)*TT + (c*CHQ + t0 + row1))*ED;
  #pragma unroll
  for (int ii = 0; ii < 2; ii++){
    int e0 = (ntb+ii)*8 + 2*t;
    float2 l0 = *(const float2*)&g_lrv[lr0 + e0];
    float2 l1 = *(const float2*)&g_lrv[lr1o + e0];
    out[ob0 + e0]   = ep[ii][0] + sc0*l0.x;
    out[ob0 + e0+1] = ep[ii][1] + sc0*l0.y;
    out[ob1 + e0]   = ep[ii][2] + sc1*l1.x;
    out[ob1 + e0+1] = ep[ii][3] + sc1*l1.y;
  }
}

// ---------------- launch ----------------
extern "C" void kernel_launch(void* const* d_in, const int* in_sizes, int n_in,
                              void* d_out, int out_size){
  const float* query = (const float*)d_in[0];
  const float* key   = (const float*)d_in[1];
  const float* value = (const float*)d_in[2];
  const float* proj  = (const float*)d_in[3];
  float* out = (float*)d_out;

  cudaFuncSetAttribute(k_phik, cudaFuncAttributeMaxDynamicSharedMemorySize, (int)sizeof(SP));
  cudaFuncSetAttribute(k_phiq, cudaFuncAttributeMaxDynamicSharedMemorySize, (int)sizeof(SQ));
  cudaFuncSetAttribute(k_local,cudaFuncAttributeMaxDynamicSharedMemorySize, (int)sizeof(S5));

  dim3 gp(8, NG);
  k_phik<<<gp, 256, sizeof(SP)>>>(key, value, proj);
  k_stab<<<NG, 32>>>();
  k_kvred<<<(NG*MF*ED+255)/256, 256>>>();
  k_ksumred<<<(NG*MF+255)/256, 256>>>();
  dim3 gq(CHQ/128, NG);
  k_phiq<<<gq, 256, sizeof(SQ)>>>(query, proj);
  dim3 g5(32, NG);
  k_local<<<g5, 256, sizeof(S5)>>>(query, key, value, out);
}

// round 7
// speedup vs baseline: 2.9503x; 1.0813x over previous
#include <cuda_runtime.h>
#include <cuda_fp16.h>
#include <math.h>
#include <math_constants.h>

#define SEQ 4096
#define TT  4096
#define CHQ 1024
#define ED  64
#define MF  128
#define NHk 8
#define NG  128
#define LOGM 4.852030263919617f

__device__ __half g_phikh[(size_t)NG*SEQ*MF];
__device__ __half g_phiqh[(size_t)NG*CHQ*MF];
__device__ float  g_tstab[NG*32];
__device__ float  g_pstab[NG*8];
__device__ float  g_stabk[NG];
__device__ float  g_kvp[(size_t)NG*8*MF*ED];
__device__ float  g_kv[NG*MF*ED];
__device__ float  g_ksump[NG*8*MF];
__device__ float  g_ksum[NG*MF];
__device__ float  g_pls[NG*CHQ];
__device__ float  g_lr1[NG*CHQ];
__device__ float  g_lrv[(size_t)NG*CHQ*ED];

__device__ __forceinline__ void mma16816(float* c, unsigned a0,unsigned a1,unsigned a2,unsigned a3,
                                         unsigned b0,unsigned b1){
  asm volatile("mma.sync.aligned.m16n8k16.row.col.f32.f16.f16.f32 "
    "{%0,%1,%2,%3},{%4,%5,%6,%7},{%8,%9},{%0,%1,%2,%3};"
    : "+f"(c[0]),"+f"(c[1]),"+f"(c[2]),"+f"(c[3])
    : "r"(a0),"r"(a1),"r"(a2),"r"(a3),"r"(b0),"r"(b1));
}
__device__ __forceinline__ unsigned ldu(const __half* p){ return *(const unsigned*)p; }
__device__ __forceinline__ void split16(float x, __half& h, __half& l){
  h = __float2half_rn(x); l = __float2half_rn(x - __half2float(h));
}

__constant__ int c_ao[3] = {0, 64, 0};
__constant__ int c_bo[3] = {0, 0, 64};

// ======== K1: logk mma + phi_k + kv mma (register acc, online rescale) ========
struct SP {
  __half Bp[128][136];
  union { __half Ak[128][136]; __half phiA[128][136]; } u;
  __half vT[64][136];
  float snorm[128];
  float wred[8];
  float ks2[256];
};

__global__ void __launch_bounds__(256,2)
k_phik(const float* __restrict__ key, const float* __restrict__ value,
       const float* __restrict__ proj){
  extern __shared__ char raw[];
  SP& sm = *reinterpret_cast<SP*>(raw);
  int g = blockIdx.y, split = blockIdx.x;
  int c = g>>5, b = (g>>3)&3, h = g&7;
  int tid = threadIdx.x, lane = tid&31, w = tid>>5;
  int gg = lane>>2, t = lane&3;

  for (int idx = tid; idx < 128*64; idx += 256){
    int m = idx>>6, e = idx&63;
    float x = proj[((size_t)c*MF+m)*ED+e];
    __half hh,ll; split16(x,hh,ll);
    sm.Bp[m][e]=hh; sm.Bp[m][64+e]=ll;
  }

  float kvacc[8][4];
  #pragma unroll
  for(int i=0;i<8;i++)
    #pragma unroll
    for(int j=0;j<4;j++) kvacc[i][j]=0.f;
  float kpriv = 0.f;
  float runstab = -CUDART_INF_F;

  for (int tile = 0; tile < 4; tile++){
    int sbase = split*512 + tile*128;
    __syncthreads();
    for (int idx = tid; idx < 128*64; idx += 256){
      int s = idx>>6, e = idx&63;
      size_t gb = (((size_t)b*SEQ + sbase + s)*NHk + h)*ED + e;
      float x = key[gb];
      __half hh,ll; split16(x,hh,ll);
      sm.u.Ak[s][e]=hh; sm.u.Ak[s][64+e]=ll;
      sm.vT[e][s] = __float2half_rn(value[gb]);
    }
    __syncthreads();
    if (tid < 128){
      float s = 0.f;
      #pragma unroll
      for (int e = 0; e < 64; e++){
        float x = __half2float(sm.u.Ak[tid][e]) + __half2float(sm.u.Ak[tid][64+e]);
        s += x*x;
      }
      sm.snorm[tid] = 0.5f*s;
    }
    __syncthreads();

    int r0 = w*16+gg, r1 = r0+8;
    float fr[2][8][4];
    #pragma unroll
    for(int nh=0;nh<2;nh++)
      #pragma unroll
      for(int i=0;i<8;i++)
        #pragma unroll
        for(int j=0;j<4;j++) fr[nh][i][j]=0.f;
    #pragma unroll
    for (int term = 0; term < 3; term++){
      int ao = c_ao[term], bo = c_bo[term];
      #pragma unroll
      for (int ks = 0; ks < 4; ks++){
        int k0 = ks*16;
        unsigned a0 = ldu(&sm.u.Ak[r0][ao+k0+2*t]);
        unsigned a1 = ldu(&sm.u.Ak[r1][ao+k0+2*t]);
        unsigned a2 = ldu(&sm.u.Ak[r0][ao+k0+2*t+8]);
        unsigned a3 = ldu(&sm.u.Ak[r1][ao+k0+2*t+8]);
        #pragma unroll
        for(int nh=0;nh<2;nh++)
          #pragma unroll
          for (int nt = 0; nt < 8; nt++){
            const __half* br = sm.Bp[nh*64 + nt*8 + gg];
            mma16816(fr[nh][nt], a0,a1,a2,a3, ldu(&br[bo+k0+2*t]), ldu(&br[bo+k0+2*t+8]));
          }
      }
    }
    float n0v = sm.snorm[r0], n1v = sm.snorm[r1];
    float mx = -CUDART_INF_F;
    #pragma unroll
    for(int nh=0;nh<2;nh++)
      #pragma unroll
      for(int nt=0;nt<8;nt++){
        fr[nh][nt][0]-=n0v; fr[nh][nt][1]-=n0v; fr[nh][nt][2]-=n1v; fr[nh][nt][3]-=n1v;
        mx = fmaxf(mx, fmaxf(fmaxf(fr[nh][nt][0],fr[nh][nt][1]),fmaxf(fr[nh][nt][2],fr[nh][nt][3])));
      }
    #pragma unroll
    for (int o=16;o>0;o>>=1) mx = fmaxf(mx, __shfl_xor_sync(0xffffffffu,mx,o));
    if (lane==0) sm.wred[w] = mx;
    __syncthreads();
    float tstab = sm.wred[0];
    #pragma unroll
    for (int q=1;q<8;q++) tstab = fmaxf(tstab, sm.wred[q]);
    if (tid==0) g_tstab[g*32 + split*4 + tile] = tstab;
    float newstab = fmaxf(runstab, tstab);
    float fo = __expf(runstab - newstab);
    float fn = __expf(tstab - newstab);
    runstab = newstab;

    size_t gr0 = ((size_t)g*SEQ + sbase + r0)*MF;
    size_t gr1 = ((size_t)g*SEQ + sbase + r1)*MF;
    #pragma unroll
    for(int nh=0;nh<2;nh++)
      #pragma unroll
      for(int nt=0;nt<8;nt++){
        int col = nh*64 + nt*8 + 2*t;
        __half h0 = __float2half_rn(__expf(fr[nh][nt][0]-tstab));
        __half h1 = __float2half_rn(__expf(fr[nh][nt][1]-tstab));
        __half h2 = __float2half_rn(__expf(fr[nh][nt][2]-tstab));
        __half h3 = __float2half_rn(__expf(fr[nh][nt][3]-tstab));
        *(__half2*)&g_phikh[gr0+col] = __halves2half2(h0,h1);
        *(__half2*)&g_phikh[gr1+col] = __halves2half2(h2,h3);
        sm.u.phiA[col][r0]=h0; sm.u.phiA[col+1][r0]=h1;
        sm.u.phiA[col][r1]=h2; sm.u.phiA[col+1][r1]=h3;
      }
    __syncthreads();

    if (tid < 128){
      const __half2* p2 = (const __half2*)&sm.u.phiA[tid][0];
      float s = 0.f;
      #pragma unroll
      for (int i = 0; i < 64; i++){ float2 f = __half22float2(p2[i]); s += f.x+f.y; }
      kpriv = kpriv*fo + fn*s;
    }

    float tmp[8][4];
    #pragma unroll
    for(int i=0;i<8;i++)
      #pragma unroll
      for(int j=0;j<4;j++) tmp[i][j]=0.f;
    #pragma unroll
    for (int ks = 0; ks < 8; ks++){
      int k0 = ks*16;
      unsigned a0 = ldu(&sm.u.phiA[w*16+gg][k0+2*t]);
      unsigned a1 = ldu(&sm.u.phiA[w*16+gg+8][k0+2*t]);
      unsigned a2 = ldu(&sm.u.phiA[w*16+gg][k0+2*t+8]);
      unsigned a3 = ldu(&sm.u.phiA[w*16+gg+8][k0+2*t+8]);
      #pragma unroll
      for (int nt = 0; nt < 8; nt++){
        const __half* br = sm.vT[nt*8+gg];
        mma16816(tmp[nt], a0,a1,a2,a3, ldu(&br[k0+2*t]), ldu(&br[k0+2*t+8]));
      }
    }
    #pragma unroll
    for(int i=0;i<8;i++)
      #pragma unroll
      for(int j=0;j<4;j++) kvacc[i][j] = kvacc[i][j]*fo + tmp[i][j]*fn;
  }

  size_t pb = ((size_t)g*8 + split)*(MF*ED);
  int m0 = w*16+gg, m1 = m0+8;
  #pragma unroll
  for (int nt = 0; nt < 8; nt++){
    int e0 = nt*8 + 2*t;
    *(float2*)&g_kvp[pb + (size_t)m0*64 + e0] = make_float2(kvacc[nt][0], kvacc[nt][1]);
    *(float2*)&g_kvp[pb + (size_t)m1*64 + e0] = make_float2(kvacc[nt][2], kvacc[nt][3]);
  }
  sm.ks2[tid] = kpriv;
  __syncthreads();
  if (tid < 128) g_ksump[((size_t)g*8 + split)*MF + tid] = sm.ks2[tid];
  if (tid == 0) g_pstab[g*8 + split] = runstab;
}

// ======== K2: stab ; K3: merged kv+ksum reduction ========
__global__ void k_stab(){
  int g = blockIdx.x, lane = threadIdx.x;
  float v = g_tstab[g*32 + lane];
  #pragma unroll
  for (int o=16;o>0;o>>=1) v = fmaxf(v, __shfl_xor_sync(0xffffffffu,v,o));
  if (lane==0) g_stabk[g] = v;
}
__global__ void k_red(){
  int i = blockIdx.x*blockDim.x + threadIdx.x;
  if (i < NG*MF*ED){
    int g = i>>13, me = i&8191;
    float stabg = g_stabk[g], s = 0.f;
    #pragma unroll
    for (int p=0;p<8;p++)
      s += g_kvp[((size_t)g*8+p)*(MF*ED)+me] * __expf(g_pstab[g*8+p]-stabg);
    g_kv[i] = s;
  } else {
    int j = i - NG*MF*ED;
    if (j < NG*MF){
      int g = j>>7, m = j&127;
      float stabg = g_stabk[g], s = 0.f;
      #pragma unroll
      for (int p=0;p<8;p++)
        s += g_ksump[(size_t)(g*8+p)*MF+m] * __expf(g_pstab[g*8+p]-stabg);
      g_ksum[j] = s;
    }
  }
}

// ======== K4: phi_q (mma), pls, lr_v (mma), lr_1 ========
struct SQ {
  __half Bp[128][136];
  union { __half Aq[128][136]; __half phiA[128][136]; } u;
  __half kvTh[64][136];
  __half kvTl[64][136];
  float snorm[128];
  float ksum[128];
};

__global__ void __launch_bounds__(256,2)
k_phiq(const float* __restrict__ query, const float* __restrict__ proj){
  extern __shared__ char raw[];
  SQ& sm = *reinterpret_cast<SQ*>(raw);
  int g = blockIdx.y;
  int c = g>>5, b = (g>>3)&3, h = g&7;
  int q0 = blockIdx.x*128;
  int tid = threadIdx.x, lane = tid&31, w = tid>>5;
  int gg = lane>>2, t = lane&3;

  for (int idx = tid; idx < 128*64; idx += 256){
    int m = idx>>6, e = idx&63;
    float x = proj[((size_t)c*MF+m)*ED+e];
    __half hh,ll; split16(x,hh,ll);
    sm.Bp[m][e]=hh; sm.Bp[m][64+e]=ll;
  }
  for (int idx = tid; idx < 128*64; idx += 256){
    int i = idx>>6, e = idx&63;
    float x = query[(((size_t)b*TT + (c*CHQ+q0+i))*NHk + h)*ED + e];
    __half hh,ll; split16(x,hh,ll);
    sm.u.Aq[i][e]=hh; sm.u.Aq[i][64+e]=ll;
  }
  for (int idx = tid; idx < 128*64; idx += 256){
    int m = idx>>6, e = idx&63;
    float x = g_kv[(size_t)g*MF*ED + m*64 + e];
    __half hh,ll; split16(x,hh,ll);
    sm.kvTh[e][m]=hh; sm.kvTl[e][m]=ll;
  }
  if (tid < 128) sm.ksum[tid] = g_ksum[g*MF+tid];
  __syncthreads();
  if (tid < 128){
    float s = 0.f;
    #pragma unroll
    for (int e = 0; e < 64; e++){
      float x = __half2float(sm.u.Aq[tid][e]) + __half2float(sm.u.Aq[tid][64+e]);
      s += x*x;
    }
    sm.snorm[tid] = 0.5f*s;
  }
  __syncthreads();

  int r0 = w*16+gg, r1 = r0+8;
  float fr[2][8][4];
  #pragma unroll
  for(int nh=0;nh<2;nh++)
    #pragma unroll
    for(int i=0;i<8;i++)
      #pragma unroll
      for(int j=0;j<4;j++) fr[nh][i][j]=0.f;
  #pragma unroll
  for (int term = 0; term < 3; term++){
    int ao = c_ao[term], bo = c_bo[term];
    #pragma unroll
    for (int ks = 0; ks < 4; ks++){
      int k0 = ks*16;
      unsigned a0 = ldu(&sm.u.Aq[r0][ao+k0+2*t]);
      unsigned a1 = ldu(&sm.u.Aq[r1][ao+k0+2*t]);
      unsigned a2 = ldu(&sm.u.Aq[r0][ao+k0+2*t+8]);
      unsigned a3 = ldu(&sm.u.Aq[r1][ao+k0+2*t+8]);
      #pragma unroll
      for(int nh=0;nh<2;nh++)
        #pragma unroll
        for (int nt = 0; nt < 8; nt++){
          const __half* br = sm.Bp[nh*64 + nt*8 + gg];
          mma16816(fr[nh][nt], a0,a1,a2,a3, ldu(&br[bo+k0+2*t]), ldu(&br[bo+k0+2*t+8]));
        }
    }
  }
  float n0v = sm.snorm[r0], n1v = sm.snorm[r1];
  float m0 = -CUDART_INF_F, m1 = -CUDART_INF_F;
  #pragma unroll
  for(int nh=0;nh<2;nh++)
    #pragma unroll
    for(int nt=0;nt<8;nt++){
      fr[nh][nt][0]-=n0v; fr[nh][nt][1]-=n0v; fr[nh][nt][2]-=n1v; fr[nh][nt][3]-=n1v;
      m0 = fmaxf(m0, fmaxf(fr[nh][nt][0], fr[nh][nt][1]));
      m1 = fmaxf(m1, fmaxf(fr[nh][nt][2], fr[nh][nt][3]));
    }
  #pragma unroll
  for (int o=1;o<=2;o<<=1){
    m0 = fmaxf(m0, __shfl_xor_sync(0xffffffffu,m0,o));
    m1 = fmaxf(m1, __shfl_xor_sync(0xffffffffu,m1,o));
  }
  float skv = g_stabk[g];
  if (t == 0){
    g_pls[(size_t)g*CHQ + q0 + r0] = m0 + skv - LOGM;
    g_pls[(size_t)g*CHQ + q0 + r1] = m1 + skv - LOGM;
  }
  __syncthreads();
  size_t gq0 = ((size_t)g*CHQ+q0+r0)*MF;
  size_t gq1 = ((size_t)g*CHQ+q0+r1)*MF;
  #pragma unroll
  for(int nh=0;nh<2;nh++)
    #pragma unroll
    for(int nt=0;nt<8;nt++){
      int col = nh*64 + nt*8 + 2*t;
      __half h0 = __float2half_rn(__expf(fr[nh][nt][0]-m0));
      __half h1 = __float2half_rn(__expf(fr[nh][nt][1]-m0));
      __half h2 = __float2half_rn(__expf(fr[nh][nt][2]-m1));
      __half h3 = __float2half_rn(__expf(fr[nh][nt][3]-m1));
      sm.u.phiA[r0][col]=h0; sm.u.phiA[r0][col+1]=h1;
      sm.u.phiA[r1][col]=h2; sm.u.phiA[r1][col+1]=h3;
      *(__half2*)&g_phiqh[gq0+col] = __halves2half2(h0,h1);
      *(__half2*)&g_phiqh[gq1+col] = __halves2half2(h2,h3);
    }
  __syncthreads();

  float acc[8][4];
  #pragma unroll
  for(int i=0;i<8;i++)
    #pragma unroll
    for(int j=0;j<4;j++) acc[i][j]=0.f;
  #pragma unroll
  for (int pass=0; pass<2; pass++){
    #pragma unroll
    for (int ks = 0; ks < 8; ks++){
      int k0 = ks*16;
      unsigned a0 = ldu(&sm.u.phiA[r0][k0+2*t]);
      unsigned a1 = ldu(&sm.u.phiA[r1][k0+2*t]);
      unsigned a2 = ldu(&sm.u.phiA[r0][k0+2*t+8]);
      unsigned a3 = ldu(&sm.u.phiA[r1][k0+2*t+8]);
      #pragma unroll
      for (int nt = 0; nt < 8; nt++){
        const __half* br = pass ? sm.kvTl[nt*8+gg] : sm.kvTh[nt*8+gg];
        mma16816(acc[nt], a0,a1,a2,a3, ldu(&br[k0+2*t]), ldu(&br[k0+2*t+8]));
      }
    }
  }
  size_t ro0 = ((size_t)g*CHQ + q0 + r0)*ED;
  size_t ro1 = ((size_t)g*CHQ + q0 + r1)*ED;
  #pragma unroll
  for (int nt = 0; nt < 8; nt++){
    int e0 = nt*8 + 2*t;
    *(float2*)&g_lrv[ro0 + e0] = make_float2(acc[nt][0], acc[nt][1]);
    *(float2*)&g_lrv[ro1 + e0] = make_float2(acc[nt][2], acc[nt][3]);
  }
  if (tid < 128){
    const __half2* p2 = (const __half2*)&sm.u.phiA[tid][0];
    float s = 0.f;
    #pragma unroll
    for (int i = 0; i < 64; i++){
      float2 f = __half22float2(p2[i]);
      s += f.x*sm.ksum[2*i] + f.y*sm.ksum[2*i+1];
    }
    g_lr1[(size_t)g*CHQ + q0 + tid] = s;
  }
}

// ======== K5: local windows via mma ========
struct S5 {
  union { __half A_s[32][200]; __half cA[32][200]; } u;
  __half B_s[64][200];
  __half vT[64][200];
  __half pqA[32][136];
  __half pkB[64][136];
  float sc[32][66];
  float dp[32][66];
  float jscale[64];
  float lnorm[32];
  float scl[32];
};

__global__ void __launch_bounds__(256,2)
k_local(const float* __restrict__ query, const float* __restrict__ key,
        const float* __restrict__ value, float* __restrict__ out){
  extern __shared__ char raw[];
  S5& sm = *reinterpret_cast<S5*>(raw);
  int g = blockIdx.y, n = blockIdx.x;
  int c = g>>5, b = (g>>3)&3, h = g&7;
  int tid = threadIdx.x, lane = tid&31, w = tid>>5;
  int gg = lane>>2, t = lane&3;
  int t0 = n*32, p0 = t0 - 16;
  float stabg = g_stabk[g];

  if (tid < 64){
    int pos = p0 + tid;
    sm.jscale[tid] = (pos >= 0) ? __expf(g_tstab[g*32 + (pos>>7)] - stabg) : 0.f;
  }
  for (int idx = tid; idx < 32*64; idx += 256){
    int qi = idx>>6, e = idx&63;
    float x = query[(((size_t)b*TT + (c*CHQ+t0+qi))*NHk + h)*ED + e];
    __half hh,ll; split16(x,hh,ll);
    sm.u.A_s[qi][e]=hh; sm.u.A_s[qi][64+e]=ll; sm.u.A_s[qi][128+e]=hh;
  }
  for (int idx = tid; idx < 64*64; idx += 256){
    int j = idx>>6, e = idx&63;
    int pos = p0 + j;
    float kx = 0.f, vx = 0.f;
    if (pos >= 0){
      size_t base = (((size_t)b*SEQ + pos)*NHk + h)*ED + e;
      kx = key[base]; vx = value[base];
    }
    __half hh,ll; split16(kx,hh,ll);
    sm.B_s[j][e]=hh; sm.B_s[j][64+e]=hh; sm.B_s[j][128+e]=ll;
    __half vh,vl; split16(vx,vh,vl);
    sm.vT[e][j]=vh; sm.vT[e][64+j]=vl; sm.vT[e][128+j]=vh;
  }
  for (int idx = tid; idx < 32*64; idx += 256){
    int qi = idx>>6, mp = idx&63;
    *(unsigned*)&sm.pqA[qi][2*mp] =
      *(const unsigned*)&g_phiqh[((size_t)g*CHQ + t0 + qi)*MF + 2*mp];
  }
  for (int idx = tid; idx < 64*64; idx += 256){
    int j = idx>>6, mp = idx&63;
    int pos = p0 + j;
    unsigned v = 0u;
    if (pos >= 0) v = *(const unsigned*)&g_phikh[((size_t)g*SEQ + pos)*MF + 2*mp];
    *(unsigned*)&sm.pkB[j][2*mp] = v;
  }
  __syncthreads();

  int mt = w&1, ntb = (w>>1)*2;
  int row0 = mt*16+gg, row1 = row0+8;

  float cs[2][4], cd[2][4];
  #pragma unroll
  for(int i=0;i<2;i++)
    #pragma unroll
    for(int j=0;j<4;j++){ cs[i][j]=0.f; cd[i][j]=0.f; }
  #pragma unroll
  for (int ks = 0; ks < 12; ks++){
    int k0 = ks*16;
    unsigned a0 = ldu(&sm.u.A_s[row0][k0+2*t]);
    unsigned a1 = ldu(&sm.u.A_s[row1][k0+2*t]);
    unsigned a2 = ldu(&sm.u.A_s[row0][k0+2*t+8]);
    unsigned a3 = ldu(&sm.u.A_s[row1][k0+2*t+8]);
    #pragma unroll
    for (int ii = 0; ii < 2; ii++){
      const __half* br = sm.B_s[(ntb+ii)*8+gg];
      mma16816(cs[ii], a0,a1,a2,a3, ldu(&br[k0+2*t]), ldu(&br[k0+2*t+8]));
    }
  }
  #pragma unroll
  for (int ks = 0; ks < 8; ks++){
    int k0 = ks*16;
    unsigned a0 = ldu(&sm.pqA[row0][k0+2*t]);
    unsigned a1 = ldu(&sm.pqA[row1][k0+2*t]);
    unsigned a2 = ldu(&sm.pqA[row0][k0+2*t+8]);
    unsigned a3 = ldu(&sm.pqA[row1][k0+2*t+8]);
    #pragma unroll
    for (int ii = 0; ii < 2; ii++){
      const __half* br = sm.pkB[(ntb+ii)*8+gg];
      mma16816(cd[ii], a0,a1,a2,a3, ldu(&br[k0+2*t]), ldu(&br[k0+2*t+8]));
    }
  }
  #pragma unroll
  for (int ii = 0; ii < 2; ii++){
    int colb = (ntb+ii)*8 + 2*t;
    #pragma unroll
    for (int cc = 0; cc < 2; cc++){
      int j = colb + cc;
      float js = sm.jscale[j];
      bool ok = (p0 + j >= 0);
      bool v0 = ok && (j>=row0) && (j<row0+32);
      bool v1 = ok && (j>=row1) && (j<row1+32);
      cs[ii][cc]   = v0 ? cs[ii][cc]      : -1e24f;
      cs[ii][2+cc] = v1 ? cs[ii][2+cc]    : -1e24f;
      cd[ii][cc]   = v0 ? cd[ii][cc]*js   : 0.f;
      cd[ii][2+cc] = v1 ? cd[ii][2+cc]*js : 0.f;
      sm.sc[row0][j] = cs[ii][cc];
      sm.sc[row1][j] = cs[ii][2+cc];
      sm.dp[row0][j] = cd[ii][cc];
      sm.dp[row1][j] = cd[ii][2+cc];
    }
  }
  __syncthreads();

  #pragma unroll
  for(int r=0;r<4;r++){
    int row = w*4+r;
    float v0 = sm.sc[row][lane], v1 = sm.sc[row][lane+32];
    float mx = fmaxf(v0,v1);
    #pragma unroll
    for(int o=16;o>0;o>>=1) mx = fmaxf(mx, __shfl_xor_sync(0xffffffffu,mx,o));
    float se = __expf(v0-mx) + __expf(v1-mx);
    #pragma unroll
    for(int o=16;o>0;o>>=1) se += __shfl_xor_sync(0xffffffffu,se,o);
    float lse = mx + __logf(se);
    float ds = sm.dp[row][lane] + sm.dp[row][lane+32];
    #pragma unroll
    for(int o=16;o>0;o>>=1) ds += __shfl_xor_sync(0xffffffffu,ds,o);
    float lr1v = g_lr1[(size_t)g*CHQ + t0 + row];
    float plsv = g_pls[(size_t)g*CHQ + t0 + row];
    float rem = fmaxf(lr1v - ds, 1e-24f);
    float bq = __logf(rem) + plsv;
    float hi = fmaxf(lse,bq), lo2 = fminf(lse,bq);
    float ln = hi + __logf(1.f + __expf(lo2-hi));
    if (lane==0){ sm.lnorm[row]=ln; sm.scl[row]=__expf(plsv-ln); }
  }
  __syncthreads();

  // cA directly from fragments (A_s overlay; all A_s mma reads are done)
  float ln0 = sm.lnorm[row0], ln1 = sm.lnorm[row1];
  float s0v = sm.scl[row0], s1v = sm.scl[row1];
  #pragma unroll
  for (int ii = 0; ii < 2; ii++){
    int colb = (ntb+ii)*8 + 2*t;
    #pragma unroll
    for (int cc = 0; cc < 2; cc++){
      int j = colb + cc;
      float c0 = __expf(cs[ii][cc]   - ln0) - s0v*cd[ii][cc];
      float c1 = __expf(cs[ii][2+cc] - ln1) - s1v*cd[ii][2+cc];
      __half ch, cl;
      split16(c0, ch, cl);
      sm.u.cA[row0][j]=ch; sm.u.cA[row0][64+j]=ch; sm.u.cA[row0][128+j]=cl;
      split16(c1, ch, cl);
      sm.u.cA[row1][j]=ch; sm.u.cA[row1][64+j]=ch; sm.u.cA[row1][128+j]=cl;
    }
  }
  __syncthreads();

  float ep[2][4];
  #pragma unroll
  for(int i=0;i<2;i++)
    #pragma unroll
    for(int j=0;j<4;j++) ep[i][j]=0.f;
  #pragma unroll
  for (int ks = 0; ks < 12; ks++){
    int k0 = ks*16;
    unsigned a0 = ldu(&sm.u.cA[row0][k0+2*t]);
    unsigned a1 = ldu(&sm.u.cA[row1][k0+2*t]);
    unsigned a2 = ldu(&sm.u.cA[row0][k0+2*t+8]);
    unsigned a3 = ldu(&sm.u.cA[row1][k0+2*t+8]);
    #pragma unroll
    for (int ii = 0; ii < 2; ii++){
      const __half* br = sm.vT[(ntb+ii)*8+gg];
      mma16816(ep[ii], a0,a1,a2,a3, ldu(&br[k0+2*t]), ldu(&br[k0+2*t+8]));
    }
  }
  float sc0 = sm.scl[row0], sc1 = sm.scl[row1];
  size_t lr0 = ((size_t)g*CHQ + t0 + row0)*ED;
  size_t lr1o = ((size_t)g*CHQ + t0 + row1)*ED;
  size_t ob0 = (((size_t)b*NHk + h)*TT + (c*CHQ + t0 + row0))*ED;
  size_t ob1 = (((size_t)b*NHk + h)*TT + (c*CHQ + t0 + row1))*ED;
  #pragma unroll
  for (int ii = 0; ii < 2; ii++){
    int e0 = (ntb+ii)*8 + 2*t;
    float2 l0 = *(const float2*)&g_lrv[lr0 + e0];
    float2 l1 = *(const float2*)&g_lrv[lr1o + e0];
    out[ob0 + e0]   = ep[ii][0] + sc0*l0.x;
    out[ob0 + e0+1] = ep[ii][1] + sc0*l0.y;
    out[ob1 + e0]   = ep[ii][2] + sc1*l1.x;
    out[ob1 + e0+1] = ep[ii][3] + sc1*l1.y;
  }
}

// ---------------- launch ----------------
extern "C" void kernel_launch(void* const* d_in, const int* in_sizes, int n_in,
                              void* d_out, int out_size){
  const float* query = (const float*)d_in[0];
  const float* key   = (const float*)d_in[1];
  const float* value = (const float*)d_in[2];
  const float* proj  = (const float*)d_in[3];
  float* out = (float*)d_out;

  cudaFuncSetAttribute(k_phik, cudaFuncAttributeMaxDynamicSharedMemorySize, (int)sizeof(SP));
  cudaFuncSetAttribute(k_phiq, cudaFuncAttributeMaxDynamicSharedMemorySize, (int)sizeof(SQ));
  cudaFuncSetAttribute(k_local,cudaFuncAttributeMaxDynamicSharedMemorySize, (int)sizeof(S5));

  dim3 gp(8, NG);
  k_phik<<<gp, 256, sizeof(SP)>>>(key, value, proj);
  k_stab<<<NG, 32>>>();
  k_red<<<(NG*MF*ED + NG*MF + 255)/256, 256>>>();
  dim3 gq(CHQ/128, NG);
  k_phiq<<<gq, 256, sizeof(SQ)>>>(query, proj);
  dim3 g5(32, NG);
  k_local<<<g5, 256, sizeof(S5)>>>(query, key, value, out);
}

// round 8
// speedup vs baseline: 2.9680x; 1.0060x over previous
#include <cuda_runtime.h>
#include <cuda_fp16.h>
#include <math.h>
#include <math_constants.h>

#define SEQ 4096
#define TT  4096
#define CHQ 1024
#define ED  64
#define MF  128
#define NHk 8
#define NG  128
#define LOGM 4.852030263919617f

__device__ __half g_phikh[(size_t)NG*SEQ*MF];
__device__ __half g_phiqh[(size_t)NG*CHQ*MF];
__device__ float  g_tstab[NG*32];
__device__ float  g_pstab[NG*8];
__device__ float  g_stabk[NG];
__device__ float  g_kvp[(size_t)NG*8*MF*ED];
__device__ float  g_kv[NG*MF*ED];
__device__ float  g_ksump[NG*8*MF];
__device__ float  g_ksum[NG*MF];
__device__ float  g_pls[NG*CHQ];
__device__ float  g_lr1[NG*CHQ];
__device__ float  g_lrv[(size_t)NG*CHQ*ED];

__device__ __forceinline__ void mma16816(float* c, unsigned a0,unsigned a1,unsigned a2,unsigned a3,
                                         unsigned b0,unsigned b1){
  asm volatile("mma.sync.aligned.m16n8k16.row.col.f32.f16.f16.f32 "
    "{%0,%1,%2,%3},{%4,%5,%6,%7},{%8,%9},{%0,%1,%2,%3};"
    : "+f"(c[0]),"+f"(c[1]),"+f"(c[2]),"+f"(c[3])
    : "r"(a0),"r"(a1),"r"(a2),"r"(a3),"r"(b0),"r"(b1));
}
__device__ __forceinline__ void ldsm4(unsigned&r0,unsigned&r1,unsigned&r2,unsigned&r3,const __half*p){
  unsigned a=(unsigned)__cvta_generic_to_shared(p);
  asm volatile("ldmatrix.sync.aligned.m8n8.x4.shared.b16 {%0,%1,%2,%3}, [%4];"
    :"=r"(r0),"=r"(r1),"=r"(r2),"=r"(r3):"r"(a));
}
__device__ __forceinline__ void ldsm4t(unsigned&r0,unsigned&r1,unsigned&r2,unsigned&r3,const __half*p){
  unsigned a=(unsigned)__cvta_generic_to_shared(p);
  asm volatile("ldmatrix.sync.aligned.m8n8.x4.trans.shared.b16 {%0,%1,%2,%3}, [%4];"
    :"=r"(r0),"=r"(r1),"=r"(r2),"=r"(r3):"r"(a));
}
__device__ __forceinline__ void split16(float x, __half& h, __half& l){
  h = __float2half_rn(x); l = __float2half_rn(x - __half2float(h));
}

__constant__ int c_ao[3] = {0, 64, 0};
__constant__ int c_bo[3] = {0, 0, 64};

// ======== K1: logk mma + phi_k + kv mma (ldmatrix, register acc) ========
struct SP {
  __half Bp[128][136];
  union { __half Ak[128][136]; __half phiS[128][136]; } u;   // phiS row-major [s][m]
  __half vT[64][136];
  float snorm[128];
  float wred[8];
  float ks2[256];
};

__global__ void __launch_bounds__(256,2)
k_phik(const float* __restrict__ key, const float* __restrict__ value,
       const float* __restrict__ proj){
  extern __shared__ char raw[];
  SP& sm = *reinterpret_cast<SP*>(raw);
  int g = blockIdx.y, split = blockIdx.x;
  int c = g>>5, b = (g>>3)&3, h = g&7;
  int tid = threadIdx.x, lane = tid&31, w = tid>>5;
  int gg = lane>>2, t = lane&3;
  int arow = (lane&7) + ((lane>>3)&1)*8, acol = (lane>>4)*8;
  int trow = (lane&7) + (lane>>4)*8,     tcol = ((lane>>3)&1)*8;

  for (int idx = tid; idx < 128*64; idx += 256){
    int m = idx>>6, e = idx&63;
    float x = proj[((size_t)c*MF+m)*ED+e];
    __half hh,ll; split16(x,hh,ll);
    sm.Bp[m][e]=hh; sm.Bp[m][64+e]=ll;
  }

  float kvacc[8][4];
  #pragma unroll
  for(int i=0;i<8;i++)
    #pragma unroll
    for(int j=0;j<4;j++) kvacc[i][j]=0.f;
  float kpriv = 0.f;
  float runstab = -CUDART_INF_F;

  for (int tile = 0; tile < 4; tile++){
    int sbase = split*512 + tile*128;
    __syncthreads();
    for (int idx = tid; idx < 128*64; idx += 256){
      int s = idx>>6, e = idx&63;
      size_t gb = (((size_t)b*SEQ + sbase + s)*NHk + h)*ED + e;
      float x = key[gb];
      __half hh,ll; split16(x,hh,ll);
      sm.u.Ak[s][e]=hh; sm.u.Ak[s][64+e]=ll;
      sm.vT[e][s] = __float2half_rn(value[gb]);
    }
    __syncthreads();
    if (tid < 128){
      float s = 0.f;
      #pragma unroll
      for (int e = 0; e < 64; e++){
        float x = __half2float(sm.u.Ak[tid][e]) + __half2float(sm.u.Ak[tid][64+e]);
        s += x*x;
      }
      sm.snorm[tid] = 0.5f*s;
    }
    __syncthreads();

    int r0 = w*16+gg, r1 = r0+8;
    float fr[16][4];
    #pragma unroll
    for(int i=0;i<16;i++)
      #pragma unroll
      for(int j=0;j<4;j++) fr[i][j]=0.f;
    #pragma unroll
    for (int term = 0; term < 3; term++){
      int ao = c_ao[term], bo = c_bo[term];
      #pragma unroll
      for (int ks = 0; ks < 4; ks++){
        int k0 = ks*16;
        unsigned a0,a1,a2,a3;
        ldsm4(a0,a1,a2,a3, &sm.u.Ak[w*16 + arow][ao + k0 + acol]);
        #pragma unroll
        for (int p = 0; p < 8; p++){
          unsigned b0,b1,b2,b3;
          ldsm4(b0,b1,b2,b3, &sm.Bp[p*16 + arow][bo + k0 + acol]);
          mma16816(fr[2*p],   a0,a1,a2,a3, b0,b2);
          mma16816(fr[2*p+1], a0,a1,a2,a3, b1,b3);
        }
      }
    }
    float n0v = sm.snorm[r0], n1v = sm.snorm[r1];
    float mx = -CUDART_INF_F;
    #pragma unroll
    for(int ft=0;ft<16;ft++){
      fr[ft][0]-=n0v; fr[ft][1]-=n0v; fr[ft][2]-=n1v; fr[ft][3]-=n1v;
      mx = fmaxf(mx, fmaxf(fmaxf(fr[ft][0],fr[ft][1]),fmaxf(fr[ft][2],fr[ft][3])));
    }
    #pragma unroll
    for (int o=16;o>0;o>>=1) mx = fmaxf(mx, __shfl_xor_sync(0xffffffffu,mx,o));
    if (lane==0) sm.wred[w] = mx;
    __syncthreads();
    float tstab = sm.wred[0];
    #pragma unroll
    for (int q=1;q<8;q++) tstab = fmaxf(tstab, sm.wred[q]);
    if (tid==0) g_tstab[g*32 + split*4 + tile] = tstab;
    float newstab = fmaxf(runstab, tstab);
    float fo = __expf(runstab - newstab);
    float fn = __expf(tstab - newstab);
    runstab = newstab;

    size_t gr0 = ((size_t)g*SEQ + sbase + r0)*MF;
    size_t gr1 = ((size_t)g*SEQ + sbase + r1)*MF;
    #pragma unroll
    for(int ft=0;ft<16;ft++){
      int col = ft*8 + 2*t;
      __half h0 = __float2half_rn(__expf(fr[ft][0]-tstab));
      __half h1 = __float2half_rn(__expf(fr[ft][1]-tstab));
      __half h2 = __float2half_rn(__expf(fr[ft][2]-tstab));
      __half h3 = __float2half_rn(__expf(fr[ft][3]-tstab));
      __half2 p01 = __halves2half2(h0,h1), p23 = __halves2half2(h2,h3);
      *(__half2*)&g_phikh[gr0+col] = p01;
      *(__half2*)&g_phikh[gr1+col] = p23;
      *(__half2*)&sm.u.phiS[r0][col] = p01;
      *(__half2*)&sm.u.phiS[r1][col] = p23;
    }
    __syncthreads();

    if (tid < 128){
      float s = 0.f;
      #pragma unroll
      for (int s_ = 0; s_ < 128; s_++) s += __half2float(sm.u.phiS[s_][tid]);
      kpriv = kpriv*fo + fn*s;
    }

    float tmp[8][4];
    #pragma unroll
    for(int i=0;i<8;i++)
      #pragma unroll
      for(int j=0;j<4;j++) tmp[i][j]=0.f;
    #pragma unroll
    for (int ks = 0; ks < 8; ks++){
      int k0 = ks*16;
      unsigned a0,a1,a2,a3;
      ldsm4t(a0,a1,a2,a3, &sm.u.phiS[k0 + trow][w*16 + tcol]);
      #pragma unroll
      for (int p = 0; p < 4; p++){
        unsigned b0,b1,b2,b3;
        ldsm4(b0,b1,b2,b3, &sm.vT[p*16 + arow][k0 + acol]);
        mma16816(tmp[2*p],   a0,a1,a2,a3, b0,b2);
        mma16816(tmp[2*p+1], a0,a1,a2,a3, b1,b3);
      }
    }
    #pragma unroll
    for(int i=0;i<8;i++)
      #pragma unroll
      for(int j=0;j<4;j++) kvacc[i][j] = kvacc[i][j]*fo + tmp[i][j]*fn;
  }

  size_t pb = ((size_t)g*8 + split)*(MF*ED);
  int m0 = w*16+gg, m1 = m0+8;
  #pragma unroll
  for (int nt = 0; nt < 8; nt++){
    int e0 = nt*8 + 2*t;
    *(float2*)&g_kvp[pb + (size_t)m0*64 + e0] = make_float2(kvacc[nt][0], kvacc[nt][1]);
    *(float2*)&g_kvp[pb + (size_t)m1*64 + e0] = make_float2(kvacc[nt][2], kvacc[nt][3]);
  }
  sm.ks2[tid] = kpriv;
  __syncthreads();
  if (tid < 128) g_ksump[((size_t)g*8 + split)*MF + tid] = sm.ks2[tid];
  if (tid == 0) g_pstab[g*8 + split] = runstab;
}

// ======== K2: stab ; K3: merged kv+ksum reduction ========
__global__ void k_stab(){
  int g = blockIdx.x, lane = threadIdx.x;
  float v = g_tstab[g*32 + lane];
  #pragma unroll
  for (int o=16;o>0;o>>=1) v = fmaxf(v, __shfl_xor_sync(0xffffffffu,v,o));
  if (lane==0) g_stabk[g] = v;
}
__global__ void k_red(){
  int i = blockIdx.x*blockDim.x + threadIdx.x;
  if (i < NG*MF*ED){
    int g = i>>13, me = i&8191;
    float stabg = g_stabk[g], s = 0.f;
    #pragma unroll
    for (int p=0;p<8;p++)
      s += g_kvp[((size_t)g*8+p)*(MF*ED)+me] * __expf(g_pstab[g*8+p]-stabg);
    g_kv[i] = s;
  } else {
    int j = i - NG*MF*ED;
    if (j < NG*MF){
      int g = j>>7, m = j&127;
      float stabg = g_stabk[g], s = 0.f;
      #pragma unroll
      for (int p=0;p<8;p++)
        s += g_ksump[(size_t)(g*8+p)*MF+m] * __expf(g_pstab[g*8+p]-stabg);
      g_ksum[j] = s;
    }
  }
}

// ======== K4: phi_q (mma), pls, lr_v (mma), lr_1 ========
struct SQ {
  __half Bp[128][136];
  union { __half Aq[128][136]; __half phiA[128][136]; } u;   // phiA row-major [q][m]
  __half kvTh[64][136];
  __half kvTl[64][136];
  float snorm[128];
  float ksum[128];
};

__global__ void __launch_bounds__(256,2)
k_phiq(const float* __restrict__ query, const float* __restrict__ proj){
  extern __shared__ char raw[];
  SQ& sm = *reinterpret_cast<SQ*>(raw);
  int g = blockIdx.y;
  int c = g>>5, b = (g>>3)&3, h = g&7;
  int q0 = blockIdx.x*128;
  int tid = threadIdx.x, lane = tid&31, w = tid>>5;
  int gg = lane>>2, t = lane&3;
  int arow = (lane&7) + ((lane>>3)&1)*8, acol = (lane>>4)*8;

  for (int idx = tid; idx < 128*64; idx += 256){
    int m = idx>>6, e = idx&63;
    float x = proj[((size_t)c*MF+m)*ED+e];
    __half hh,ll; split16(x,hh,ll);
    sm.Bp[m][e]=hh; sm.Bp[m][64+e]=ll;
  }
  for (int idx = tid; idx < 128*64; idx += 256){
    int i = idx>>6, e = idx&63;
    float x = query[(((size_t)b*TT + (c*CHQ+q0+i))*NHk + h)*ED + e];
    __half hh,ll; split16(x,hh,ll);
    sm.u.Aq[i][e]=hh; sm.u.Aq[i][64+e]=ll;
  }
  for (int idx = tid; idx < 128*64; idx += 256){
    int m = idx>>6, e = idx&63;
    float x = g_kv[(size_t)g*MF*ED + m*64 + e];
    __half hh,ll; split16(x,hh,ll);
    sm.kvTh[e][m]=hh; sm.kvTl[e][m]=ll;
  }
  if (tid < 128) sm.ksum[tid] = g_ksum[g*MF+tid];
  __syncthreads();
  if (tid < 128){
    float s = 0.f;
    #pragma unroll
    for (int e = 0; e < 64; e++){
      float x = __half2float(sm.u.Aq[tid][e]) + __half2float(sm.u.Aq[tid][64+e]);
      s += x*x;
    }
    sm.snorm[tid] = 0.5f*s;
  }
  __syncthreads();

  int r0 = w*16+gg, r1 = r0+8;
  float fr[16][4];
  #pragma unroll
  for(int i=0;i<16;i++)
    #pragma unroll
    for(int j=0;j<4;j++) fr[i][j]=0.f;
  #pragma unroll
  for (int term = 0; term < 3; term++){
    int ao = c_ao[term], bo = c_bo[term];
    #pragma unroll
    for (int ks = 0; ks < 4; ks++){
      int k0 = ks*16;
      unsigned a0,a1,a2,a3;
      ldsm4(a0,a1,a2,a3, &sm.u.Aq[w*16 + arow][ao + k0 + acol]);
      #pragma unroll
      for (int p = 0; p < 8; p++){
        unsigned b0,b1,b2,b3;
        ldsm4(b0,b1,b2,b3, &sm.Bp[p*16 + arow][bo + k0 + acol]);
        mma16816(fr[2*p],   a0,a1,a2,a3, b0,b2);
        mma16816(fr[2*p+1], a0,a1,a2,a3, b1,b3);
      }
    }
  }
  float n0v = sm.snorm[r0], n1v = sm.snorm[r1];
  float m0 = -CUDART_INF_F, m1 = -CUDART_INF_F;
  #pragma unroll
  for(int ft=0;ft<16;ft++){
    fr[ft][0]-=n0v; fr[ft][1]-=n0v; fr[ft][2]-=n1v; fr[ft][3]-=n1v;
    m0 = fmaxf(m0, fmaxf(fr[ft][0], fr[ft][1]));
    m1 = fmaxf(m1, fmaxf(fr[ft][2], fr[ft][3]));
  }
  #pragma unroll
  for (int o=1;o<=2;o<<=1){
    m0 = fmaxf(m0, __shfl_xor_sync(0xffffffffu,m0,o));
    m1 = fmaxf(m1, __shfl_xor_sync(0xffffffffu,m1,o));
  }
  float skv = g_stabk[g];
  if (t == 0){
    g_pls[(size_t)g*CHQ + q0 + r0] = m0 + skv - LOGM;
    g_pls[(size_t)g*CHQ + q0 + r1] = m1 + skv - LOGM;
  }
  __syncthreads();
  size_t gq0 = ((size_t)g*CHQ+q0+r0)*MF;
  size_t gq1 = ((size_t)g*CHQ+q0+r1)*MF;
  #pragma unroll
  for(int ft=0;ft<16;ft++){
    int col = ft*8 + 2*t;
    __half h0 = __float2half_rn(__expf(fr[ft][0]-m0));
    __half h1 = __float2half_rn(__expf(fr[ft][1]-m0));
    __half h2 = __float2half_rn(__expf(fr[ft][2]-m1));
    __half h3 = __float2half_rn(__expf(fr[ft][3]-m1));
    __half2 p01 = __halves2half2(h0,h1), p23 = __halves2half2(h2,h3);
    *(__half2*)&sm.u.phiA[r0][col] = p01;
    *(__half2*)&sm.u.phiA[r1][col] = p23;
    *(__half2*)&g_phiqh[gq0+col] = p01;
    *(__half2*)&g_phiqh[gq1+col] = p23;
  }
  __syncthreads();

  float acc[8][4];
  #pragma unroll
  for(int i=0;i<8;i++)
    #pragma unroll
    for(int j=0;j<4;j++) acc[i][j]=0.f;
  #pragma unroll
  for (int pass=0; pass<2; pass++){
    #pragma unroll
    for (int ks = 0; ks < 8; ks++){
      int k0 = ks*16;
      unsigned a0,a1,a2,a3;
      ldsm4(a0,a1,a2,a3, &sm.u.phiA[w*16 + arow][k0 + acol]);
      #pragma unroll
      for (int p = 0; p < 4; p++){
        const __half* br = pass ? &sm.kvTl[p*16 + arow][k0 + acol]
                                : &sm.kvTh[p*16 + arow][k0 + acol];
        unsigned b0,b1,b2,b3;
        ldsm4(b0,b1,b2,b3, br);
        mma16816(acc[2*p],   a0,a1,a2,a3, b0,b2);
        mma16816(acc[2*p+1], a0,a1,a2,a3, b1,b3);
      }
    }
  }
  size_t ro0 = ((size_t)g*CHQ + q0 + r0)*ED;
  size_t ro1 = ((size_t)g*CHQ + q0 + r1)*ED;
  #pragma unroll
  for (int nt = 0; nt < 8; nt++){
    int e0 = nt*8 + 2*t;
    *(float2*)&g_lrv[ro0 + e0] = make_float2(acc[nt][0], acc[nt][1]);
    *(float2*)&g_lrv[ro1 + e0] = make_float2(acc[nt][2], acc[nt][3]);
  }
  if (tid < 128){
    const __half2* p2 = (const __half2*)&sm.u.phiA[tid][0];
    float s = 0.f;
    #pragma unroll
    for (int i = 0; i < 64; i++){
      float2 f = __half22float2(p2[i]);
      s += f.x*sm.ksum[2*i] + f.y*sm.ksum[2*i+1];
    }
    g_lr1[(size_t)g*CHQ + q0 + tid] = s;
  }
}

// ======== K5: local windows via mma (ldmatrix) ========
struct S5 {
  union { __half A_s[32][200]; __half cA[32][200]; } u;
  __half B_s[64][200];
  __half vT[64][200];
  __half pqA[32][136];
  __half pkB[64][136];
  float sc[32][66];
  float dp[32][66];
  float jscale[64];
  float lnorm[32];
  float scl[32];
};

__global__ void __launch_bounds__(256,2)
k_local(const float* __restrict__ query, const float* __restrict__ key,
        const float* __restrict__ value, float* __restrict__ out){
  extern __shared__ char raw[];
  S5& sm = *reinterpret_cast<S5*>(raw);
  int g = blockIdx.y, n = blockIdx.x;
  int c = g>>5, b = (g>>3)&3, h = g&7;
  int tid = threadIdx.x, lane = tid&31, w = tid>>5;
  int t = lane&3;
  int arow = (lane&7) + ((lane>>3)&1)*8, acol = (lane>>4)*8;
  int t0 = n*32, p0 = t0 - 16;
  float stabg = g_stabk[g];

  if (tid < 64){
    int pos = p0 + tid;
    sm.jscale[tid] = (pos >= 0) ? __expf(g_tstab[g*32 + (pos>>7)] - stabg) : 0.f;
  }
  for (int idx = tid; idx < 32*64; idx += 256){
    int qi = idx>>6, e = idx&63;
    float x = query[(((size_t)b*TT + (c*CHQ+t0+qi))*NHk + h)*ED + e];
    __half hh,ll; split16(x,hh,ll);
    sm.u.A_s[qi][e]=hh; sm.u.A_s[qi][64+e]=ll; sm.u.A_s[qi][128+e]=hh;
  }
  for (int idx = tid; idx < 64*64; idx += 256){
    int j = idx>>6, e = idx&63;
    int pos = p0 + j;
    float kx = 0.f, vx = 0.f;
    if (pos >= 0){
      size_t base = (((size_t)b*SEQ + pos)*NHk + h)*ED + e;
      kx = key[base]; vx = value[base];
    }
    __half hh,ll; split16(kx,hh,ll);
    sm.B_s[j][e]=hh; sm.B_s[j][64+e]=hh; sm.B_s[j][128+e]=ll;
    __half vh,vl; split16(vx,vh,vl);
    sm.vT[e][j]=vh; sm.vT[e][64+j]=vl; sm.vT[e][128+j]=vh;
  }
  for (int idx = tid; idx < 32*64; idx += 256){
    int qi = idx>>6, mp = idx&63;
    *(unsigned*)&sm.pqA[qi][2*mp] =
      *(const unsigned*)&g_phiqh[((size_t)g*CHQ + t0 + qi)*MF + 2*mp];
  }
  for (int idx = tid; idx < 64*64; idx += 256){
    int j = idx>>6, mp = idx&63;
    int pos = p0 + j;
    unsigned v = 0u;
    if (pos >= 0) v = *(const unsigned*)&g_phikh[((size_t)g*SEQ + pos)*MF + 2*mp];
    *(unsigned*)&sm.pkB[j][2*mp] = v;
  }
  __syncthreads();

  int mt = w&1, ntb = (w>>1)*2;
  int row0 = mt*16 + (lane>>2), row1 = row0+8;

  float cs[2][4], cd[2][4];
  #pragma unroll
  for(int i=0;i<2;i++)
    #pragma unroll
    for(int j=0;j<4;j++){ cs[i][j]=0.f; cd[i][j]=0.f; }
  #pragma unroll
  for (int ks = 0; ks < 12; ks++){
    int k0 = ks*16;
    unsigned a0,a1,a2,a3, b0,b1,b2,b3;
    ldsm4(a0,a1,a2,a3, &sm.u.A_s[mt*16 + arow][k0 + acol]);
    ldsm4(b0,b1,b2,b3, &sm.B_s[(w>>1)*16 + arow][k0 + acol]);
    mma16816(cs[0], a0,a1,a2,a3, b0,b2);
    mma16816(cs[1], a0,a1,a2,a3, b1,b3);
  }
  #pragma unroll
  for (int ks = 0; ks < 8; ks++){
    int k0 = ks*16;
    unsigned a0,a1,a2,a3, b0,b1,b2,b3;
    ldsm4(a0,a1,a2,a3, &sm.pqA[mt*16 + arow][k0 + acol]);
    ldsm4(b0,b1,b2,b3, &sm.pkB[(w>>1)*16 + arow][k0 + acol]);
    mma16816(cd[0], a0,a1,a2,a3, b0,b2);
    mma16816(cd[1], a0,a1,a2,a3, b1,b3);
  }
  #pragma unroll
  for (int ii = 0; ii < 2; ii++){
    int colb = (ntb+ii)*8 + 2*t;
    #pragma unroll
    for (int cc = 0; cc < 2; cc++){
      int j = colb + cc;
      float js = sm.jscale[j];
      bool ok = (p0 + j >= 0);
      bool v0 = ok && (j>=row0) && (j<row0+32);
      bool v1 = ok && (j>=row1) && (j<row1+32);
      cs[ii][cc]   = v0 ? cs[ii][cc]      : -1e24f;
      cs[ii][2+cc] = v1 ? cs[ii][2+cc]    : -1e24f;
      cd[ii][cc]   = v0 ? cd[ii][cc]*js   : 0.f;
      cd[ii][2+cc] = v1 ? cd[ii][2+cc]*js : 0.f;
      sm.sc[row0][j] = cs[ii][cc];
      sm.sc[row1][j] = cs[ii][2+cc];
      sm.dp[row0][j] = cd[ii][cc];
      sm.dp[row1][j] = cd[ii][2+cc];
    }
  }
  __syncthreads();

  #pragma unroll
  for(int r=0;r<4;r++){
    int row = w*4+r;
    float v0 = sm.sc[row][lane], v1 = sm.sc[row][lane+32];
    float mx = fmaxf(v0,v1);
    #pragma unroll
    for(int o=16;o>0;o>>=1) mx = fmaxf(mx, __shfl_xor_sync(0xffffffffu,mx,o));
    float se = __expf(v0-mx) + __expf(v1-mx);
    #pragma unroll
    for(int o=16;o>0;o>>=1) se += __shfl_xor_sync(0xffffffffu,se,o);
    float lse = mx + __logf(se);
    float ds = sm.dp[row][lane] + sm.dp[row][lane+32];
    #pragma unroll
    for(int o=16;o>0;o>>=1) ds += __shfl_xor_sync(0xffffffffu,ds,o);
    float lr1v = g_lr1[(size_t)g*CHQ + t0 + row];
    float plsv = g_pls[(size_t)g*CHQ + t0 + row];
    float rem = fmaxf(lr1v - ds, 1e-24f);
    float bq = __logf(rem) + plsv;
    float hi = fmaxf(lse,bq), lo2 = fminf(lse,bq);
    float ln = hi + __logf(1.f + __expf(lo2-hi));
    if (lane==0){ sm.lnorm[row]=ln; sm.scl[row]=__expf(plsv-ln); }
  }
  __syncthreads();

  float ln0 = sm.lnorm[row0], ln1 = sm.lnorm[row1];
  float s0v = sm.scl[row0], s1v = sm.scl[row1];
  #pragma unroll
  for (int ii = 0; ii < 2; ii++){
    int colb = (ntb+ii)*8 + 2*t;
    #pragma unroll
    for (int cc = 0; cc < 2; cc++){
      int j = colb + cc;
      float c0 = __expf(cs[ii][cc]   - ln0) - s0v*cd[ii][cc];
      float c1 = __expf(cs[ii][2+cc] - ln1) - s1v*cd[ii][2+cc];
      __half ch, cl;
      split16(c0, ch, cl);
      sm.u.cA[row0][j]=ch; sm.u.cA[row0][64+j]=ch; sm.u.cA[row0][128+j]=cl;
      split16(c1, ch, cl);
      sm.u.cA[row1][j]=ch; sm.u.cA[row1][64+j]=ch; sm.u.cA[row1][128+j]=cl;
    }
  }
  __syncthreads();

  float ep[2][4];
  #pragma unroll
  for(int i=0;i<2;i++)
    #pragma unroll
    for(int j=0;j<4;j++) ep[i][j]=0.f;
  #pragma unroll
  for (int ks = 0; ks < 12; ks++){
    int k0 = ks*16;
    unsigned a0,a1,a2,a3, b0,b1,b2,b3;
    ldsm4(a0,a1,a2,a3, &sm.u.cA[mt*16 + arow][k0 + acol]);
    ldsm4(b0,b1,b2,b3, &sm.vT[(w>>1)*16 + arow][k0 + acol]);
    mma16816(ep[0], a0,a1,a2,a3, b0,b2);
    mma16816(ep[1], a0,a1,a2,a3, b1,b3);
  }
  float sc0 = sm.scl[row0], sc1 = sm.scl[row1];
  size_t lr0 = ((size_t)g*CHQ + t0 + row0)*ED;
  size_t lr1o = ((size_t)g*CHQ + t0 + row1)*ED;
  size_t ob0 = (((size_t)b*NHk + h)*TT + (c*CHQ + t0 + row0))*ED;
  size_t ob1 = (((size_t)b*NHk + h)*TT + (c*CHQ + t0 + row1))*ED;
  #pragma unroll
  for (int ii = 0; ii < 2; ii++){
    int e0 = (ntb+ii)*8 + 2*t;
    float2 l0 = *(const float2*)&g_lrv[lr0 + e0];
    float2 l1 = *(const float2*)&g_lrv[lr1o + e0];
    out[ob0 + e0]   = ep[ii][0] + sc0*l0.x;
    out[ob0 + e0+1] = ep[ii][1] + sc0*l0.y;
    out[ob1 + e0]   = ep[ii][2] + sc1*l1.x;
    out[ob1 + e0+1] = ep[ii][3] + sc1*l1.y;
  }
}

// ---------------- launch ----------------
extern "C" void kernel_launch(void* const* d_in, const int* in_sizes, int n_in,
                              void* d_out, int out_size){
  const float* query = (const float*)d_in[0];
  const float* key   = (const float*)d_in[1];
  const float* value = (const float*)d_in[2];
  const float* proj  = (const float*)d_in[3];
  float* out = (float*)d_out;

  cudaFuncSetAttribute(k_phik, cudaFuncAttributeMaxDynamicSharedMemorySize, (int)sizeof(SP));
  cudaFuncSetAttribute(k_phiq, cudaFuncAttributeMaxDynamicSharedMemorySize, (int)sizeof(SQ));
  cudaFuncSetAttribute(k_local,cudaFuncAttributeMaxDynamicSharedMemorySize, (int)sizeof(S5));

  dim3 gp(8, NG);
  k_phik<<<gp, 256, sizeof(SP)>>>(key, value, proj);
  k_stab<<<NG, 32>>>();
  k_red<<<(NG*MF*ED + NG*MF + 255)/256, 256>>>();
  dim3 gq(CHQ/128, NG);
  k_phiq<<<gq, 256, sizeof(SQ)>>>(query, proj);
  dim3 g5(32, NG);
  k_local<<<g5, 256, sizeof(S5)>>>(query, key, value, out);
}